// round 14
// baseline (speedup 1.0000x reference)
#include <cuda_runtime.h>
#include <cstdint>
#include <math.h>

#define TOKS 2048
#define HID  2048
#define NEXP 64
#define IDIM 768
#define TOPK 8
#define NROWS 16384   // TOKS*TOPK

// ---- arch-feature gate: tcgen05 only exists in the sm_103a-specific pass ----
#define HAS_TC 0
#ifdef __CUDA_ARCH_FEAT_SM103_ALL
#undef HAS_TC
#define HAS_TC 1
#endif
#ifdef __CUDA_ARCH_HAS_FEATURE__
#if __CUDA_ARCH_HAS_FEATURE__(SM103_ALL)
#undef HAS_TC
#define HAS_TC 1
#endif
#endif

// ---------------- scratch (device globals; no allocation allowed) ----------
__device__ int   g_counts[NEXP];
__device__ int   g_offsets[NEXP + 1];
__device__ int   g_sel[NROWS];
__device__ float g_wt[NROWS];
__device__ int   g_row_token[NROWS];
__device__ int   g_pos_of[NROWS];
__device__ float g_act[(size_t)NROWS * IDIM];
__device__ float g_down[(size_t)NROWS * HID];

// ---------------- generic helpers -------------------------------------------
__device__ __forceinline__ uint32_t smem_u32(const void* p) {
    uint32_t a;
    asm("{ .reg .u64 t; cvta.to.shared.u64 t, %1; cvt.u32.u64 %0, t; }"
        : "=r"(a) : "l"(p));
    return a;
}
__device__ __forceinline__ uint32_t tf32r(float x) {
    uint32_t u;
    asm("cvt.rna.tf32.f32 %0, %1;" : "=r"(u) : "f"(x));
    return u;
}
__device__ __forceinline__ uint64_t mk_policy_ef() {
    uint64_t pol;
    asm("createpolicy.fractional.L2::evict_first.b64 %0, 1.0;" : "=l"(pol));
    return pol;
}
__device__ __forceinline__ float ldg_ef(const float* p, uint64_t pol) {
    float v;
    asm volatile("ld.global.nc.L2::cache_hint.f32 %0, [%1], %2;"
                 : "=f"(v) : "l"(p), "l"(pol));
    return v;
}
#define SWZ128(o) ((o) ^ (((o) >> 3) & 0x70))

// packed f32x2 (family-wide on sm_10x, fine for compute_103)
__device__ __forceinline__ void fma2(unsigned long long& d, unsigned long long a,
                                     unsigned long long b) {
    asm("fma.rn.f32x2 %0, %1, %2, %0;" : "+l"(d) : "l"(a), "l"(b));
}
__device__ __forceinline__ unsigned long long splat2(float a) {
    unsigned long long r;
    unsigned int u = __float_as_uint(a);
    asm("mov.b64 %0, {%1, %1};" : "=l"(r) : "r"(u));
    return r;
}
__device__ __forceinline__ float2 unpack2(unsigned long long v) {
    unsigned int lo, hi;
    asm("mov.b64 {%0, %1}, %2;" : "=r"(lo), "=r"(hi) : "l"(v));
    return make_float2(__uint_as_float(lo), __uint_as_float(hi));
}

#if HAS_TC
// ---------------- tcgen05 helpers (guarded) ----------------------------------
__device__ __forceinline__ uint32_t elect_one() {
    uint32_t p;
    asm volatile("{\n\t.reg .pred p;\n\telect.sync _|p, 0xFFFFFFFF;\n\t"
                 "selp.b32 %0, 1, 0, p;\n\t}" : "=r"(p));
    return p;
}
#define MBAR_INIT(a, c) \
    asm volatile("mbarrier.init.shared.b64 [%0], %1;" :: "r"(a), "r"(c) : "memory")
#define MBAR_INVAL(a) \
    asm volatile("mbarrier.inval.shared.b64 [%0];" :: "r"(a) : "memory")
#define MBAR_WAIT(a, par) do {                                              \
    uint32_t _m = (a), _p = (par), _d;                                      \
    asm volatile("{\n\t.reg .pred p;\n\t"                                   \
        "mbarrier.try_wait.parity.acquire.cta.shared::cta.b64 p, [%1], %2;\n\t" \
        "selp.b32 %0, 1, 0, p;\n\t}" : "=r"(_d) : "r"(_m), "r"(_p) : "memory"); \
    if (!_d) {                                                              \
        asm volatile("{\n\t.reg .pred P1;\n\t"                              \
            "W%=:\n\t"                                                       \
            "mbarrier.try_wait.parity.acquire.cta.shared::cta.b64 P1, [%0], %1, 0x989680;\n\t" \
            "@P1 bra.uni D%=;\n\tbra.uni W%=;\n\tD%=:\n\t}"                  \
            :: "r"(_m), "r"(_p) : "memory");                                \
    }                                                                       \
} while (0)

#define TC_ALLOC(sa, n) \
    asm volatile("tcgen05.alloc.cta_group::1.sync.aligned.shared::cta.b32 [%0], %1;" \
                 :: "r"(sa), "r"((uint32_t)(n)) : "memory")
#define TC_DEALLOC(t, n) \
    asm volatile("tcgen05.dealloc.cta_group::1.sync.aligned.b32 %0, %1;" \
                 :: "r"(t), "r"((uint32_t)(n)))
#define TC_RELINQ() \
    asm volatile("tcgen05.relinquish_alloc_permit.cta_group::1.sync.aligned;")
#define TC_COMMIT(mb) \
    asm volatile("tcgen05.commit.cta_group::1.mbarrier::arrive::one.shared::cluster.b64 [%0];" \
                 :: "r"(mb) : "memory")
#define TC_FENCE_BEFORE() asm volatile("tcgen05.fence::before_thread_sync;" ::: "memory")
#define TC_FENCE_AFTER()  asm volatile("tcgen05.fence::after_thread_sync;" ::: "memory")
#define TC_WAIT_LD()      asm volatile("tcgen05.wait::ld.sync.aligned;" ::: "memory")
#define FENCE_ASYNC()     asm volatile("fence.proxy.async.shared::cta;" ::: "memory")

#define LDTM32(r, a)                                                         \
    asm volatile("tcgen05.ld.sync.aligned.32x32b.x32.b32 "                   \
        "{%0,%1,%2,%3,%4,%5,%6,%7,%8,%9,%10,%11,%12,%13,%14,%15,"            \
        "%16,%17,%18,%19,%20,%21,%22,%23,%24,%25,%26,%27,%28,%29,%30,%31}, [%32];" \
        : "=r"((r)[0]),"=r"((r)[1]),"=r"((r)[2]),"=r"((r)[3]),               \
          "=r"((r)[4]),"=r"((r)[5]),"=r"((r)[6]),"=r"((r)[7]),               \
          "=r"((r)[8]),"=r"((r)[9]),"=r"((r)[10]),"=r"((r)[11]),             \
          "=r"((r)[12]),"=r"((r)[13]),"=r"((r)[14]),"=r"((r)[15]),           \
          "=r"((r)[16]),"=r"((r)[17]),"=r"((r)[18]),"=r"((r)[19]),           \
          "=r"((r)[20]),"=r"((r)[21]),"=r"((r)[22]),"=r"((r)[23]),           \
          "=r"((r)[24]),"=r"((r)[25]),"=r"((r)[26]),"=r"((r)[27]),           \
          "=r"((r)[28]),"=r"((r)[29]),"=r"((r)[30]),"=r"((r)[31])            \
        : "r"(a))

__device__ __forceinline__ uint64_t mk_desc(uint32_t addr) {
    const uint64_t base = (uint64_t(2) << 61) | (uint64_t(1) << 46)
                        | (uint64_t(64) << 32) | (uint64_t(1) << 16);
    return base | ((uint64_t)(addr >> 4) & 0x3FFF);
}
// idesc: c=F32, a/b=TF32, M=128; N configurable
#define IDESC_TF32_N128 ((1u << 4) | (2u << 7) | (2u << 10) | (16u << 17) | (8u << 24))
#define IDESC_TF32_N64  ((1u << 4) | (2u << 7) | (2u << 10) | (8u << 17)  | (8u << 24))
__device__ __forceinline__ void mma_tf32_n128(uint32_t d, uint64_t a, uint64_t b,
                                              uint32_t en) {
    asm volatile("{\n\t.reg .pred p;\n\tsetp.ne.u32 p, %5, 0;\n\t"
        "tcgen05.mma.cta_group::1.kind::tf32 [%0], %1, %2, %3, {%4,%4,%4,%4}, p;\n\t}"
        :: "r"(d), "l"(a), "l"(b), "r"(IDESC_TF32_N128), "r"(0u), "r"(en)
        : "memory");
}
__device__ __forceinline__ void mma_tf32_n64(uint32_t d, uint64_t a, uint64_t b,
                                             uint32_t en) {
    asm volatile("{\n\t.reg .pred p;\n\tsetp.ne.u32 p, %5, 0;\n\t"
        "tcgen05.mma.cta_group::1.kind::tf32 [%0], %1, %2, %3, {%4,%4,%4,%4}, p;\n\t}"
        :: "r"(d), "l"(a), "l"(b), "r"(IDESC_TF32_N64), "r"(0u), "r"(en)
        : "memory");
}
#endif // HAS_TC

// ---------------- setup kernels ----------------------------------------------
__global__ void zero_kernel() {
    int t = threadIdx.x;
    if (t < NEXP) g_counts[t] = 0;
}

// merged scan + scatter
__global__ __launch_bounds__(512)
void scatter2_kernel() {
    __shared__ int soff[NEXP];
    __shared__ int scur[NEXP];
    int tid = threadIdx.x;
    if (tid == 0) {
        int s = 0;
        for (int e = 0; e < NEXP; e++) {
            soff[e] = s; g_offsets[e] = s; s += g_counts[e];
        }
        g_offsets[NEXP] = s;
    }
    if (tid < NEXP) scur[tid] = 0;
    __syncthreads();
#pragma unroll
    for (int it = 0; it < NROWS / 512; it++) {
        int i = it * 512 + tid;
        int e = g_sel[i];
        int p = soff[e] + atomicAdd(&scur[e], 1);
        g_row_token[p] = i >> 3;
        g_pos_of[i] = p;
    }
}

// ---------------- router -----------------------------------------------------
__global__ void router_kernel(const float* __restrict__ x,
                              const float* __restrict__ gw) {
    __shared__ float xs[16][64];
    __shared__ float gws[64][64];
    __shared__ float lg[16][64];
    int tid = threadIdx.x;
    int t0 = blockIdx.x * 16;
    int tok = tid >> 4, eg = tid & 15;
    float a0 = 0.f, a1 = 0.f, a2 = 0.f, a3 = 0.f;
    for (int h0 = 0; h0 < HID; h0 += 64) {
#pragma unroll
        for (int i = 0; i < 4; i++) {
            int idx = i * 256 + tid;
            int row = idx >> 4, col = (idx & 15) * 4;
            *(float4*)&gws[row][col] =
                *(const float4*)(gw + (size_t)(h0 + row) * NEXP + col);
        }
        {
            int row = tid >> 4, col = (tid & 15) * 4;
            *(float4*)&xs[row][col] =
                *(const float4*)(x + (size_t)(t0 + row) * HID + h0 + col);
        }
        __syncthreads();
#pragma unroll 8
        for (int hh = 0; hh < 64; hh++) {
            float xv = xs[tok][hh];
            float4 g4 = *(const float4*)&gws[hh][eg * 4];
            a0 += xv * g4.x; a1 += xv * g4.y; a2 += xv * g4.z; a3 += xv * g4.w;
        }
        __syncthreads();
    }
    lg[tok][eg * 4 + 0] = a0; lg[tok][eg * 4 + 1] = a1;
    lg[tok][eg * 4 + 2] = a2; lg[tok][eg * 4 + 3] = a3;
    __syncthreads();
    if (tid < 16) {
        int t = t0 + tid;
        float vals[TOPK]; int sel[TOPK];
#pragma unroll
        for (int k = 0; k < TOPK; k++) {
            float best = -3.4e38f; int bi = 0;
            for (int e2 = 0; e2 < NEXP; e2++) {
                float v = lg[tid][e2];
                if (v > best) { best = v; bi = e2; }
            }
            vals[k] = best; sel[k] = bi;
            lg[tid][bi] = -3.4e38f;
        }
        float m = vals[0], ex[TOPK], s = 0.f;
#pragma unroll
        for (int k = 0; k < TOPK; k++) { ex[k] = expf(vals[k] - m); s += ex[k]; }
        float inv = 1.0f / s;
#pragma unroll
        for (int k = 0; k < TOPK; k++) {
            g_sel[t * TOPK + k] = sel[k];
            g_wt[t * TOPK + k] = ex[k] * inv;
            atomicAdd(&g_counts[sel[k]], 1);
        }
    }
}

// dynamic smem sizes
#define SM1_TOT (2048 + 2 * (32768 + 8192 + 8192))   // 100352 -> occ 2
#define SM2_TOT (2048 + 2 * (32768 + 16384))         // 100352 -> occ 2

// ---------------- grouped GEMM 1: act = silu(x@Wg)*(x@Wu) --------------------
// grid (IDIM/64, NEXP), 256 threads, occ 2. N=64 tiles, TMEM 256 cols.
__global__ __launch_bounds__(256, 2)
void gemm1_tc(const float* __restrict__ x,
              const float* __restrict__ Wg,
              const float* __restrict__ Wu) {
#if HAS_TC
    extern __shared__ char smem[];
    int e = blockIdx.y, ci = blockIdx.x;
    int n = g_counts[e];
    if (n == 0) return;
    int off = g_offsets[e];
    int tid = threadIdx.x;
    uint32_t sb = smem_u32(smem);
    uint32_t mb0 = sb + 8, mb1 = sb + 16;
    uint32_t aA0 = (sb + 1024 + 1023) & ~1023u;
    uint32_t aBG0 = aA0 + 32768, aBU0 = aBG0 + 8192;
    uint32_t aA1 = aBU0 + 8192;
    uint32_t aBG1 = aA1 + 32768, aBU1 = aBG1 + 8192;
    char* base = smem - sb;
    uint64_t pol = mk_policy_ef();

    if (tid < 32) TC_ALLOC(sb, 256);
    if (tid == 0) { MBAR_INIT(mb0, 1); MBAR_INIT(mb1, 1); }
    __syncthreads();
    uint32_t tmem;
    asm volatile("ld.shared.b32 %0, [%1];" : "=r"(tmem) : "r"(sb));

    const float* wgb = Wg + (size_t)e * HID * IDIM + ci * 64;
    const float* wub = Wu + (size_t)e * HID * IDIM + ci * 64;
    const int nn = tid & 63;            // B n-row
    const int qr = tid >> 6;            // quarter: owns k-cells qr*2, qr*2+1
    const int kcA = tid & 7;            // A k-cell
    uint32_t ph0 = 0, ph1 = 0;
    int used0 = 0, used1 = 0;

// TMEM cols: [0,64) gate Mg0, [64,128) gate Mg1, [128,192) up Mg0, [192,256) up Mg1
#define G1_CHUNK(CH, AA, ABG, ABU, MB, PH, USED, FIRSTC) do {               \
    int k0 = (CH) * 32;                                                     \
    float4 av[8];                                                           \
    _Pragma("unroll")                                                       \
    for (int i = 0; i < 8; i++)                                             \
        av[i] = aptr[i] ? *(const float4*)(aptr[i] + k0 + kcA * 4)          \
                        : make_float4(0.f, 0.f, 0.f, 0.f);                  \
    float bg[2][4], bu[2][4];                                               \
    _Pragma("unroll")                                                       \
    for (int c = 0; c < 2; c++) {                                           \
        int kc = qr * 2 + c;                                                \
        const float* wg4 = wgb + (size_t)(k0 + kc * 4) * IDIM + nn;         \
        const float* wu4 = wub + (size_t)(k0 + kc * 4) * IDIM + nn;         \
        _Pragma("unroll")                                                   \
        for (int j = 0; j < 4; j++) {                                       \
            bg[c][j] = ldg_ef(wg4 + (size_t)j * IDIM, pol);                 \
            bu[c][j] = ldg_ef(wu4 + (size_t)j * IDIM, pol);                 \
        }                                                                   \
    }                                                                       \
    if (USED) { MBAR_WAIT(MB, PH); PH ^= 1; }                               \
    USED = 1;                                                               \
    _Pragma("unroll")                                                       \
    for (int i = 0; i < 8; i++) {                                           \
        int row = i * 32 + (tid >> 3);                                      \
        uint32_t o = SWZ128((uint32_t)(row * 128 + kcA * 16));              \
        uint4 v = { tf32r(av[i].x), tf32r(av[i].y),                         \
                    tf32r(av[i].z), tf32r(av[i].w) };                       \
        *(uint4*)(base + (AA) + o) = v;                                     \
    }                                                                       \
    _Pragma("unroll")                                                       \
    for (int c = 0; c < 2; c++) {                                           \
        int kc = qr * 2 + c;                                                \
        uint32_t o = SWZ128((uint32_t)(nn * 128 + kc * 16));                \
        uint4 vg = { tf32r(bg[c][0]), tf32r(bg[c][1]),                      \
                     tf32r(bg[c][2]), tf32r(bg[c][3]) };                    \
        uint4 vu = { tf32r(bu[c][0]), tf32r(bu[c][1]),                      \
                     tf32r(bu[c][2]), tf32r(bu[c][3]) };                    \
        *(uint4*)(base + (ABG) + o) = vg;                                   \
        *(uint4*)(base + (ABU) + o) = vu;                                   \
    }                                                                       \
    __syncthreads();                                                        \
    if (tid < 32) {                                                         \
        FENCE_ASYNC();                                                      \
        if (elect_one()) {                                                  \
            uint64_t da0 = mk_desc(AA);                                     \
            uint64_t da1 = mk_desc((AA) + 128 * 128);                       \
            uint64_t dbg = mk_desc(ABG);                                    \
            uint64_t dbu = mk_desc(ABU);                                    \
            _Pragma("unroll")                                               \
            for (int s = 0; s < 4; s++) {                                   \
                uint32_t en = ((FIRSTC) && s == 0) ? 0u : 1u;               \
                uint64_t so = 2 * s;                                        \
                mma_tf32_n64(tmem + 0,   da0 + so, dbg + so, en);           \
                mma_tf32_n64(tmem + 64,  da1 + so, dbg + so, en);           \
                mma_tf32_n64(tmem + 128, da0 + so, dbu + so, en);           \
                mma_tf32_n64(tmem + 192, da1 + so, dbu + so, en);           \
            }                                                               \
            TC_COMMIT(MB);                                                  \
        }                                                                   \
    }                                                                       \
} while (0)

    for (int row0 = 0; row0 < n; row0 += 256) {
        const float* aptr[8];
#pragma unroll
        for (int i = 0; i < 8; i++) {
            int gr = row0 + i * 32 + (tid >> 3);
            aptr[i] = (gr < n) ? x + (size_t)g_row_token[off + gr] * HID : nullptr;
        }
        for (int ch = 0; ch < HID / 32; ch += 2) {
            G1_CHUNK(ch,     aA0, aBG0, aBU0, mb0, ph0, used0, ch == 0);
            G1_CHUNK(ch + 1, aA1, aBG1, aBU1, mb1, ph1, used1, 0);
        }
        MBAR_WAIT(mb1, ph1); ph1 ^= 1; used1 = 0;
        TC_FENCE_AFTER();
        int rg = tid >> 7;
        uint32_t wo = ((uint32_t)((tid >> 5) & 3)) << 21;
        int grow = row0 + rg * 128 + (tid & 127);
        bool valid = grow < n;
        size_t orow = (size_t)(off + grow) * IDIM + ci * 64;
#pragma unroll
        for (int cb = 0; cb < 64; cb += 32) {
            uint32_t rgv[32], ruv[32];
            LDTM32(rgv, tmem + rg * 64 + cb + wo);
            LDTM32(ruv, tmem + 128 + rg * 64 + cb + wo);
            TC_WAIT_LD();
            if (valid) {
#pragma unroll
                for (int c = 0; c < 32; c += 4) {
                    uint4 o;
                    float gg, uu, a;
                    gg = __uint_as_float(rgv[c + 0]); uu = __uint_as_float(ruv[c + 0]);
                    a = (gg / (1.f + expf(-gg))) * uu; o.x = tf32r(a);
                    gg = __uint_as_float(rgv[c + 1]); uu = __uint_as_float(ruv[c + 1]);
                    a = (gg / (1.f + expf(-gg))) * uu; o.y = tf32r(a);
                    gg = __uint_as_float(rgv[c + 2]); uu = __uint_as_float(ruv[c + 2]);
                    a = (gg / (1.f + expf(-gg))) * uu; o.z = tf32r(a);
                    gg = __uint_as_float(rgv[c + 3]); uu = __uint_as_float(ruv[c + 3]);
                    a = (gg / (1.f + expf(-gg))) * uu; o.w = tf32r(a);
                    *(uint4*)(g_act + orow + cb + c) = o;
                }
            }
        }
        TC_FENCE_BEFORE();
        __syncthreads();
    }
#undef G1_CHUNK
    if (tid == 0) { MBAR_INVAL(mb0); MBAR_INVAL(mb1); }
    __syncthreads();
    if (tid < 32) { TC_RELINQ(); TC_DEALLOC(tmem, 256); }
#else
    // -------- SIMT fallback (64-col ci tiles) --------
    int e = blockIdx.y;
    int n = g_counts[e];
    if (n == 0) return;
    int off = g_offsets[e];
    int ci = blockIdx.x;
    __shared__ float As[16][128];
    __shared__ float Bgs[16][64];
    __shared__ float Bus[16][64];
    int tid = threadIdx.x;
    int tr = tid & 31, tc = tid >> 5;
    int lr = tid >> 1, lh = (tid & 1) * 8;
    int bkk = tid >> 4, bc = (tid & 15) * 4;
    const float* wg = Wg + (size_t)e * HID * IDIM + ci * 64;
    const float* wu = Wu + (size_t)e * HID * IDIM + ci * 64;
    for (int row0 = 0; row0 < n; row0 += 128) {
        int rows = min(128, n - row0);
        const float* xrow = (lr < rows)
            ? (x + (size_t)g_row_token[off + row0 + lr] * HID) : nullptr;
        unsigned long long accg[4][4], accu[4][4];
#pragma unroll
        for (int r = 0; r < 4; r++)
#pragma unroll
            for (int p = 0; p < 4; p++) { accg[r][p] = 0ull; accu[r][p] = 0ull; }
        for (int k0 = 0; k0 < HID; k0 += 16) {
            float4 av0 = {0,0,0,0}, av1 = {0,0,0,0};
            if (xrow) {
                av0 = *(const float4*)(xrow + k0 + lh);
                av1 = *(const float4*)(xrow + k0 + lh + 4);
            }
            float4 bgv = *(const float4*)(wg + (size_t)(k0 + bkk) * IDIM + bc);
            float4 buv = *(const float4*)(wu + (size_t)(k0 + bkk) * IDIM + bc);
            __syncthreads();
            As[lh + 0][lr] = av0.x; As[lh + 1][lr] = av0.y;
            As[lh + 2][lr] = av0.z; As[lh + 3][lr] = av0.w;
            As[lh + 4][lr] = av1.x; As[lh + 5][lr] = av1.y;
            As[lh + 6][lr] = av1.z; As[lh + 7][lr] = av1.w;
            *(float4*)&Bgs[bkk][bc] = bgv;
            *(float4*)&Bus[bkk][bc] = buv;
            __syncthreads();
#pragma unroll
            for (int kk = 0; kk < 16; kk++) {
                float4 av = *(const float4*)&As[kk][tr * 4];
                ulonglong2 bg0 = *(const ulonglong2*)&Bgs[kk][tc * 8];
                ulonglong2 bg1 = *(const ulonglong2*)&Bgs[kk][tc * 8 + 4];
                ulonglong2 bu0 = *(const ulonglong2*)&Bus[kk][tc * 8];
                ulonglong2 bu1 = *(const ulonglong2*)&Bus[kk][tc * 8 + 4];
                unsigned long long aa[4] =
                    { splat2(av.x), splat2(av.y), splat2(av.z), splat2(av.w) };
#pragma unroll
                for (int r = 0; r < 4; r++) {
                    fma2(accg[r][0], aa[r], bg0.x);
                    fma2(accg[r][1], aa[r], bg0.y);
                    fma2(accg[r][2], aa[r], bg1.x);
                    fma2(accg[r][3], aa[r], bg1.y);
                    fma2(accu[r][0], aa[r], bu0.x);
                    fma2(accu[r][1], aa[r], bu0.y);
                    fma2(accu[r][2], aa[r], bu1.x);
                    fma2(accu[r][3], aa[r], bu1.y);
                }
            }
        }
#pragma unroll
        for (int r = 0; r < 4; r++) {
            int lrow = tr * 4 + r;
            if (lrow < rows) {
                float* dst = g_act + (size_t)(off + row0 + lrow) * IDIM
                             + ci * 64 + tc * 8;
#pragma unroll
                for (int p = 0; p < 4; p++) {
                    float2 g = unpack2(accg[r][p]);
                    float2 u = unpack2(accu[r][p]);
                    dst[p * 2 + 0] = (g.x / (1.0f + expf(-g.x))) * u.x;
                    dst[p * 2 + 1] = (g.y / (1.0f + expf(-g.y))) * u.y;
                }
            }
        }
    }
#endif
}

// ---------------- grouped GEMM 2: down = act @ Wd ----------------------------
// grid (HID/128, NEXP), 256 threads, 2 CTAs/SM.
__global__ __launch_bounds__(256, 2)
void gemm2_tc(const float* __restrict__ Wd) {
#if HAS_TC
    extern __shared__ char smem[];
    int e = blockIdx.y, ci = blockIdx.x;
    int n = g_counts[e];
    if (n == 0) return;
    int off = g_offsets[e];
    int tid = threadIdx.x;
    uint32_t sb = smem_u32(smem);
    uint32_t mb0 = sb + 8, mb1 = sb + 16;
    uint32_t aA0 = (sb + 1024 + 1023) & ~1023u;
    uint32_t aB0 = aA0 + 32768;
    uint32_t aA1 = aB0 + 16384;
    uint32_t aB1 = aA1 + 32768;
    char* base = smem - sb;
    uint64_t pol = mk_policy_ef();

    if (tid < 32) TC_ALLOC(sb, 256);
    if (tid == 0) { MBAR_INIT(mb0, 1); MBAR_INIT(mb1, 1); }
    __syncthreads();
    uint32_t tmem;
    asm volatile("ld.shared.b32 %0, [%1];" : "=r"(tmem) : "r"(sb));

    const float* wdb = Wd + (size_t)e * IDIM * HID + ci * 128;
    const int nn = tid & 127;
    const int kcA = tid & 7;
    uint32_t ph0 = 0, ph1 = 0;
    int used0 = 0, used1 = 0;

#define G2_CHUNK(CH, AA, AB, MB, PH, USED, FIRSTC) do {                     \
    int k0 = (CH) * 32;                                                     \
    uint4 av[8];                                                            \
    _Pragma("unroll")                                                       \
    for (int i = 0; i < 8; i++)                                             \
        av[i] = aptr[i] ? *(const uint4*)(aptr[i] + k0 + kcA * 4)           \
                        : make_uint4(0u, 0u, 0u, 0u);                       \
    float bv[4][4];                                                         \
    _Pragma("unroll")                                                       \
    for (int i = 0; i < 4; i++) {                                           \
        int kc = i * 2 + (tid >> 7);                                        \
        const float* wb = wdb + (size_t)(k0 + kc * 4) * HID + nn;           \
        _Pragma("unroll")                                                   \
        for (int j = 0; j < 4; j++) bv[i][j] = ldg_ef(wb + (size_t)j * HID, pol); \
    }                                                                       \
    if (USED) { MBAR_WAIT(MB, PH); PH ^= 1; }                               \
    USED = 1;                                                               \
    _Pragma("unroll")                                                       \
    for (int i = 0; i < 8; i++) {                                           \
        int row = i * 32 + (tid >> 3);                                      \
        uint32_t o = SWZ128((uint32_t)(row * 128 + kcA * 16));              \
        *(uint4*)(base + (AA) + o) = av[i];                                 \
    }                                                                       \
    _Pragma("unroll")                                                       \
    for (int i = 0; i < 4; i++) {                                           \
        int kc = i * 2 + (tid >> 7);                                        \
        uint32_t o = SWZ128((uint32_t)(nn * 128 + kc * 16));                \
        uint4 v = { tf32r(bv[i][0]), tf32r(bv[i][1]),                       \
                    tf32r(bv[i][2]), tf32r(bv[i][3]) };                     \
        *(uint4*)(base + (AB) + o) = v;                                     \
    }                                                                       \
    __syncthreads();                                                        \
    if (tid < 32) {                                                         \
        FENCE_ASYNC();                                                      \
        if (elect_one()) {                                                  \
            uint64_t da0 = mk_desc(AA);                                     \
            uint64_t da1 = mk_desc((AA) + 128 * 128);                       \
            uint64_t db  = mk_desc(AB);                                     \
            _Pragma("unroll")                                               \
            for (int s = 0; s < 4; s++) {                                   \
                uint32_t en = ((FIRSTC) && s == 0) ? 0u : 1u;               \
                uint64_t so = 2 * s;                                        \
                mma_tf32_n128(tmem + 0,   da0 + so, db + so, en);           \
                mma_tf32_n128(tmem + 128, da1 + so, db + so, en);           \
            }                                                               \
            TC_COMMIT(MB);                                                  \
        }                                                                   \
    }                                                                       \
} while (0)

    for (int row0 = 0; row0 < n; row0 += 256) {
        const float* aptr[8];
#pragma unroll
        for (int i = 0; i < 8; i++) {
            int gr = row0 + i * 32 + (tid >> 3);
            aptr[i] = (gr < n) ? g_act + (size_t)(off + gr) * IDIM : nullptr;
        }
        for (int ch = 0; ch < IDIM / 32; ch += 2) {
            G2_CHUNK(ch,     aA0, aB0, mb0, ph0, used0, ch == 0);
            G2_CHUNK(ch + 1, aA1, aB1, mb1, ph1, used1, 0);
        }
        MBAR_WAIT(mb1, ph1); ph1 ^= 1; used1 = 0;
        TC_FENCE_AFTER();
        int rg = tid >> 7;
        uint32_t wo = ((uint32_t)((tid >> 5) & 3)) << 21;
        int grow = row0 + rg * 128 + (tid & 127);
        bool valid = grow < n;
        size_t orow = (size_t)(off + grow) * HID + ci * 128;
#pragma unroll
        for (int cb = 0; cb < 128; cb += 32) {
            uint32_t dv[32];
            LDTM32(dv, tmem + rg * 128 + cb + wo);
            TC_WAIT_LD();
            if (valid) {
#pragma unroll
                for (int c = 0; c < 32; c += 4) {
                    uint4 o = { dv[c], dv[c + 1], dv[c + 2], dv[c + 3] };
                    *(uint4*)(g_down + orow + cb + c) = o;
                }
            }
        }
        TC_FENCE_BEFORE();
        __syncthreads();
    }
#undef G2_CHUNK
    if (tid == 0) { MBAR_INVAL(mb0); MBAR_INVAL(mb1); }
    __syncthreads();
    if (tid < 32) { TC_RELINQ(); TC_DEALLOC(tmem, 256); }
#else
    // -------- SIMT fallback --------
    int e = blockIdx.y;
    int n = g_counts[e];
    if (n == 0) return;
    int off = g_offsets[e];
    int ci = blockIdx.x;
    __shared__ float As[16][128];
    __shared__ float Bs[16][64];
    int tid = threadIdx.x;
    int tr = tid & 31, tc = tid >> 5;
    int lr = tid >> 1, lh = (tid & 1) * 8;
    int bkk = tid >> 4, bc = (tid & 15) * 4;
    for (int half = 0; half < 2; half++) {
        const float* wd = Wd + (size_t)e * IDIM * HID + ci * 128 + half * 64;
        for (int row0 = 0; row0 < n; row0 += 128) {
            int rows = min(128, n - row0);
            const float* arow = (lr < rows)
                ? (g_act + (size_t)(off + row0 + lr) * IDIM) : nullptr;
            unsigned long long acc[4][4];
#pragma unroll
            for (int r = 0; r < 4; r++)
#pragma unroll
                for (int p = 0; p < 4; p++) acc[r][p] = 0ull;
            for (int k0 = 0; k0 < IDIM; k0 += 16) {
                float4 av0 = {0,0,0,0}, av1 = {0,0,0,0};
                if (arow) {
                    av0 = *(const float4*)(arow + k0 + lh);
                    av1 = *(const float4*)(arow + k0 + lh + 4);
                }
                float4 bd = *(const float4*)(wd + (size_t)(k0 + bkk) * HID + bc);
                __syncthreads();
                As[lh + 0][lr] = av0.x; As[lh + 1][lr] = av0.y;
                As[lh + 2][lr] = av0.z; As[lh + 3][lr] = av0.w;
                As[lh + 4][lr] = av1.x; As[lh + 5][lr] = av1.y;
                As[lh + 6][lr] = av1.z; As[lh + 7][lr] = av1.w;
                *(float4*)&Bs[bkk][bc] = bd;
                __syncthreads();
#pragma unroll
                for (int kk = 0; kk < 16; kk++) {
                    float4 av = *(const float4*)&As[kk][tr * 4];
                    ulonglong2 b0 = *(const ulonglong2*)&Bs[kk][tc * 8];
                    ulonglong2 b1 = *(const ulonglong2*)&Bs[kk][tc * 8 + 4];
                    unsigned long long aa[4] =
                        { splat2(av.x), splat2(av.y), splat2(av.z), splat2(av.w) };
#pragma unroll
                    for (int r = 0; r < 4; r++) {
                        fma2(acc[r][0], aa[r], b0.x);
                        fma2(acc[r][1], aa[r], b0.y);
                        fma2(acc[r][2], aa[r], b1.x);
                        fma2(acc[r][3], aa[r], b1.y);
                    }
                }
            }
#pragma unroll
            for (int r = 0; r < 4; r++) {
                int lrow = tr * 4 + r;
                if (lrow < rows) {
                    float* dst = g_down + (size_t)(off + row0 + lrow) * HID
                                 + ci * 128 + half * 64 + tc * 8;
                    unsigned long long* dq = (unsigned long long*)dst;
#pragma unroll
                    for (int p = 0; p < 4; p++) dq[p] = acc[r][p];
                }
            }
        }
    }
#endif
}

// ---------------- combine ----------------------------------------------------
__global__ __launch_bounds__(512)
void combine_kernel(float* __restrict__ out) {
    int t = blockIdx.x;
    int h4 = threadIdx.x;
    __shared__ float sw[TOPK];
    __shared__ int   sp[TOPK];
    if (threadIdx.x < TOPK) {
        sw[threadIdx.x] = g_wt[t * TOPK + threadIdx.x];
        sp[threadIdx.x] = g_pos_of[t * TOPK + threadIdx.x];
    }
    __syncthreads();
    float4 acc = make_float4(0.f, 0.f, 0.f, 0.f);
#pragma unroll
    for (int k = 0; k < TOPK; k++) {
        float w = sw[k];
        float4 v = ((const float4*)(g_down + (size_t)sp[k] * HID))[h4];
        acc.x += w * v.x; acc.y += w * v.y; acc.z += w * v.z; acc.w += w * v.w;
    }
    ((float4*)(out + (size_t)t * HID))[h4] = acc;
}

// ---------------- launch -----------------------------------------------------
extern "C" void kernel_launch(void* const* d_in, const int* in_sizes, int n_in,
                              void* d_out, int out_size) {
    const float* x  = (const float*)d_in[0];
    const float* gw = (const float*)d_in[1];
    const float* Wg = (const float*)d_in[2];
    const float* Wu = (const float*)d_in[3];
    const float* Wd = (const float*)d_in[4];
    float* out = (float*)d_out;

    cudaFuncSetAttribute(gemm1_tc, cudaFuncAttributeMaxDynamicSharedMemorySize, SM1_TOT);
    cudaFuncSetAttribute(gemm2_tc, cudaFuncAttributeMaxDynamicSharedMemorySize, SM2_TOT);

    zero_kernel<<<1, 64>>>();
    router_kernel<<<TOKS / 16, 256>>>(x, gw);
    scatter2_kernel<<<1, 512>>>();
    gemm1_tc<<<dim3(IDIM / 64, NEXP), 256, SM1_TOT>>>(x, Wg, Wu);
    gemm2_tc<<<dim3(HID / 128, NEXP), 256, SM2_TOT>>>(Wd);
    combine_kernel<<<TOKS, 512>>>(out);
}

// round 15
// speedup vs baseline: 1.1435x; 1.1435x over previous
#include <cuda_runtime.h>
#include <cstdint>
#include <math.h>

#define TOKS 2048
#define HID  2048
#define NEXP 64
#define IDIM 768
#define TOPK 8
#define NROWS 16384   // TOKS*TOPK

// ---- arch-feature gate: tcgen05 only exists in the sm_103a-specific pass ----
#define HAS_TC 0
#ifdef __CUDA_ARCH_FEAT_SM103_ALL
#undef HAS_TC
#define HAS_TC 1
#endif
#ifdef __CUDA_ARCH_HAS_FEATURE__
#if __CUDA_ARCH_HAS_FEATURE__(SM103_ALL)
#undef HAS_TC
#define HAS_TC 1
#endif
#endif

// ---------------- scratch (device globals; no allocation allowed) ----------
__device__ int   g_counts[NEXP];
__device__ int   g_offsets[NEXP + 1];
__device__ int   g_sel[NROWS];
__device__ float g_wt[NROWS];
__device__ int   g_row_token[NROWS];
__device__ int   g_pos_of[NROWS];
__device__ float g_act[(size_t)NROWS * IDIM];
__device__ float g_down[(size_t)NROWS * HID];

// ---------------- generic helpers -------------------------------------------
__device__ __forceinline__ uint32_t smem_u32(const void* p) {
    uint32_t a;
    asm("{ .reg .u64 t; cvta.to.shared.u64 t, %1; cvt.u32.u64 %0, t; }"
        : "=r"(a) : "l"(p));
    return a;
}
__device__ __forceinline__ uint32_t tf32r(float x) {
    uint32_t u;
    asm("cvt.rna.tf32.f32 %0, %1;" : "=r"(u) : "f"(x));
    return u;
}
__device__ __forceinline__ uint64_t mk_policy_ef() {
    uint64_t pol;
    asm("createpolicy.fractional.L2::evict_first.b64 %0, 1.0;" : "=l"(pol));
    return pol;
}
__device__ __forceinline__ float ldg_ef(const float* p, uint64_t pol) {
    float v;
    asm volatile("ld.global.nc.L2::cache_hint.f32 %0, [%1], %2;"
                 : "=f"(v) : "l"(p), "l"(pol));
    return v;
}
#define SWZ128(o) ((o) ^ (((o) >> 3) & 0x70))

// packed f32x2 (family-wide on sm_10x, fine for compute_103)
__device__ __forceinline__ void fma2(unsigned long long& d, unsigned long long a,
                                     unsigned long long b) {
    asm("fma.rn.f32x2 %0, %1, %2, %0;" : "+l"(d) : "l"(a), "l"(b));
}
__device__ __forceinline__ unsigned long long splat2(float a) {
    unsigned long long r;
    unsigned int u = __float_as_uint(a);
    asm("mov.b64 %0, {%1, %1};" : "=l"(r) : "r"(u));
    return r;
}
__device__ __forceinline__ float2 unpack2(unsigned long long v) {
    unsigned int lo, hi;
    asm("mov.b64 {%0, %1}, %2;" : "=r"(lo), "=r"(hi) : "l"(v));
    return make_float2(__uint_as_float(lo), __uint_as_float(hi));
}

#if HAS_TC
// ---------------- tcgen05 helpers (guarded) ----------------------------------
__device__ __forceinline__ uint32_t elect_one() {
    uint32_t p;
    asm volatile("{\n\t.reg .pred p;\n\telect.sync _|p, 0xFFFFFFFF;\n\t"
                 "selp.b32 %0, 1, 0, p;\n\t}" : "=r"(p));
    return p;
}
#define MBAR_INIT(a, c) \
    asm volatile("mbarrier.init.shared.b64 [%0], %1;" :: "r"(a), "r"(c) : "memory")
#define MBAR_INVAL(a) \
    asm volatile("mbarrier.inval.shared.b64 [%0];" :: "r"(a) : "memory")
#define MBAR_WAIT(a, par) do {                                              \
    uint32_t _m = (a), _p = (par), _d;                                      \
    asm volatile("{\n\t.reg .pred p;\n\t"                                   \
        "mbarrier.try_wait.parity.acquire.cta.shared::cta.b64 p, [%1], %2;\n\t" \
        "selp.b32 %0, 1, 0, p;\n\t}" : "=r"(_d) : "r"(_m), "r"(_p) : "memory"); \
    if (!_d) {                                                              \
        asm volatile("{\n\t.reg .pred P1;\n\t"                              \
            "W%=:\n\t"                                                       \
            "mbarrier.try_wait.parity.acquire.cta.shared::cta.b64 P1, [%0], %1, 0x989680;\n\t" \
            "@P1 bra.uni D%=;\n\tbra.uni W%=;\n\tD%=:\n\t}"                  \
            :: "r"(_m), "r"(_p) : "memory");                                \
    }                                                                       \
} while (0)

#define TC_ALLOC(sa, n) \
    asm volatile("tcgen05.alloc.cta_group::1.sync.aligned.shared::cta.b32 [%0], %1;" \
                 :: "r"(sa), "r"((uint32_t)(n)) : "memory")
#define TC_DEALLOC(t, n) \
    asm volatile("tcgen05.dealloc.cta_group::1.sync.aligned.b32 %0, %1;" \
                 :: "r"(t), "r"((uint32_t)(n)))
#define TC_RELINQ() \
    asm volatile("tcgen05.relinquish_alloc_permit.cta_group::1.sync.aligned;")
#define TC_COMMIT(mb) \
    asm volatile("tcgen05.commit.cta_group::1.mbarrier::arrive::one.shared::cluster.b64 [%0];" \
                 :: "r"(mb) : "memory")
#define TC_FENCE_BEFORE() asm volatile("tcgen05.fence::before_thread_sync;" ::: "memory")
#define TC_FENCE_AFTER()  asm volatile("tcgen05.fence::after_thread_sync;" ::: "memory")
#define TC_WAIT_LD()      asm volatile("tcgen05.wait::ld.sync.aligned;" ::: "memory")
#define FENCE_ASYNC()     asm volatile("fence.proxy.async.shared::cta;" ::: "memory")

#define LDTM32(r, a)                                                         \
    asm volatile("tcgen05.ld.sync.aligned.32x32b.x32.b32 "                   \
        "{%0,%1,%2,%3,%4,%5,%6,%7,%8,%9,%10,%11,%12,%13,%14,%15,"            \
        "%16,%17,%18,%19,%20,%21,%22,%23,%24,%25,%26,%27,%28,%29,%30,%31}, [%32];" \
        : "=r"((r)[0]),"=r"((r)[1]),"=r"((r)[2]),"=r"((r)[3]),               \
          "=r"((r)[4]),"=r"((r)[5]),"=r"((r)[6]),"=r"((r)[7]),               \
          "=r"((r)[8]),"=r"((r)[9]),"=r"((r)[10]),"=r"((r)[11]),             \
          "=r"((r)[12]),"=r"((r)[13]),"=r"((r)[14]),"=r"((r)[15]),           \
          "=r"((r)[16]),"=r"((r)[17]),"=r"((r)[18]),"=r"((r)[19]),           \
          "=r"((r)[20]),"=r"((r)[21]),"=r"((r)[22]),"=r"((r)[23]),           \
          "=r"((r)[24]),"=r"((r)[25]),"=r"((r)[26]),"=r"((r)[27]),           \
          "=r"((r)[28]),"=r"((r)[29]),"=r"((r)[30]),"=r"((r)[31])            \
        : "r"(a))

__device__ __forceinline__ uint64_t mk_desc(uint32_t addr) {
    const uint64_t base = (uint64_t(2) << 61) | (uint64_t(1) << 46)
                        | (uint64_t(64) << 32) | (uint64_t(1) << 16);
    return base | ((uint64_t)(addr >> 4) & 0x3FFF);
}
#define IDESC_TF32_128 ((1u << 4) | (2u << 7) | (2u << 10) | (16u << 17) | (8u << 24))
__device__ __forceinline__ void mma_tf32(uint32_t d, uint64_t a, uint64_t b,
                                         uint32_t en) {
    asm volatile("{\n\t.reg .pred p;\n\tsetp.ne.u32 p, %5, 0;\n\t"
        "tcgen05.mma.cta_group::1.kind::tf32 [%0], %1, %2, %3, {%4,%4,%4,%4}, p;\n\t}"
        :: "r"(d), "l"(a), "l"(b), "r"(IDESC_TF32_128), "r"(0u), "r"(en)
        : "memory");
}
#endif // HAS_TC

// ---------------- setup kernels ----------------------------------------------
__global__ void zero_kernel() {
    int t = threadIdx.x;
    if (t < NEXP) g_counts[t] = 0;
}

// merged scan + scatter
__global__ __launch_bounds__(512)
void scatter2_kernel() {
    __shared__ int soff[NEXP];
    __shared__ int scur[NEXP];
    int tid = threadIdx.x;
    if (tid == 0) {
        int s = 0;
        for (int e = 0; e < NEXP; e++) {
            soff[e] = s; g_offsets[e] = s; s += g_counts[e];
        }
        g_offsets[NEXP] = s;
    }
    if (tid < NEXP) scur[tid] = 0;
    __syncthreads();
#pragma unroll
    for (int it = 0; it < NROWS / 512; it++) {
        int i = it * 512 + tid;
        int e = g_sel[i];
        int p = soff[e] + atomicAdd(&scur[e], 1);
        g_row_token[p] = i >> 3;
        g_pos_of[i] = p;
    }
}

// ---------------- router -----------------------------------------------------
__global__ void router_kernel(const float* __restrict__ x,
                              const float* __restrict__ gw) {
    __shared__ float xs[16][64];
    __shared__ float gws[64][64];
    __shared__ float lg[16][64];
    int tid = threadIdx.x;
    int t0 = blockIdx.x * 16;
    int tok = tid >> 4, eg = tid & 15;
    float a0 = 0.f, a1 = 0.f, a2 = 0.f, a3 = 0.f;
    for (int h0 = 0; h0 < HID; h0 += 64) {
#pragma unroll
        for (int i = 0; i < 4; i++) {
            int idx = i * 256 + tid;
            int row = idx >> 4, col = (idx & 15) * 4;
            *(float4*)&gws[row][col] =
                *(const float4*)(gw + (size_t)(h0 + row) * NEXP + col);
        }
        {
            int row = tid >> 4, col = (tid & 15) * 4;
            *(float4*)&xs[row][col] =
                *(const float4*)(x + (size_t)(t0 + row) * HID + h0 + col);
        }
        __syncthreads();
#pragma unroll 8
        for (int hh = 0; hh < 64; hh++) {
            float xv = xs[tok][hh];
            float4 g4 = *(const float4*)&gws[hh][eg * 4];
            a0 += xv * g4.x; a1 += xv * g4.y; a2 += xv * g4.z; a3 += xv * g4.w;
        }
        __syncthreads();
    }
    lg[tok][eg * 4 + 0] = a0; lg[tok][eg * 4 + 1] = a1;
    lg[tok][eg * 4 + 2] = a2; lg[tok][eg * 4 + 3] = a3;
    __syncthreads();
    if (tid < 16) {
        int t = t0 + tid;
        float vals[TOPK]; int sel[TOPK];
#pragma unroll
        for (int k = 0; k < TOPK; k++) {
            float best = -3.4e38f; int bi = 0;
            for (int e2 = 0; e2 < NEXP; e2++) {
                float v = lg[tid][e2];
                if (v > best) { best = v; bi = e2; }
            }
            vals[k] = best; sel[k] = bi;
            lg[tid][bi] = -3.4e38f;
        }
        float m = vals[0], ex[TOPK], s = 0.f;
#pragma unroll
        for (int k = 0; k < TOPK; k++) { ex[k] = expf(vals[k] - m); s += ex[k]; }
        float inv = 1.0f / s;
#pragma unroll
        for (int k = 0; k < TOPK; k++) {
            g_sel[t * TOPK + k] = sel[k];
            g_wt[t * TOPK + k] = ex[k] * inv;
            atomicAdd(&g_counts[sel[k]], 1);
        }
    }
}

// dynamic smem: header 2KB + double-buffered tiles
#define SM1_TOT (2048 + 2 * (32768 + 16384 + 16384))   // 133120
#define SM2_TOT (2048 + 2 * (32768 + 16384))           // 100352

// ---------------- grouped GEMM 1: act = silu(x@Wg)*(x@Wu) --------------------
// grid (IDIM/128, NEXP), 256 threads. Double-buffered mainloop.
__global__ __launch_bounds__(256)
void gemm1_tc(const float* __restrict__ x,
              const float* __restrict__ Wg,
              const float* __restrict__ Wu) {
#if HAS_TC
    extern __shared__ char smem[];
    int e = blockIdx.y, ci = blockIdx.x;
    int n = g_counts[e];
    if (n == 0) return;
    int off = g_offsets[e];
    int tid = threadIdx.x;
    uint32_t sb = smem_u32(smem);
    uint32_t mb0 = sb + 8, mb1 = sb + 16;
    uint32_t aA0 = (sb + 1024 + 1023) & ~1023u;
    uint32_t aBG0 = aA0 + 32768, aBU0 = aBG0 + 16384;
    uint32_t aA1 = aBU0 + 16384;
    uint32_t aBG1 = aA1 + 32768, aBU1 = aBG1 + 16384;
    char* base = smem - sb;     // char* such that base + smem_addr = generic ptr
    uint64_t pol = mk_policy_ef();

    if (tid < 32) TC_ALLOC(sb, 512);
    if (tid == 0) { MBAR_INIT(mb0, 1); MBAR_INIT(mb1, 1); }
    __syncthreads();
    uint32_t tmem;
    asm volatile("ld.shared.b32 %0, [%1];" : "=r"(tmem) : "r"(sb));

    const float* wgb = Wg + (size_t)e * HID * IDIM + ci * 128;
    const float* wub = Wu + (size_t)e * HID * IDIM + ci * 128;
    const int nn = tid & 127;
    const int kcA = tid & 7;
    uint32_t ph0 = 0, ph1 = 0;
    int used0 = 0, used1 = 0;

#define G1_CHUNK(CH, AA, ABG, ABU, MB, PH, USED, FIRSTC) do {               \
    int k0 = (CH) * 32;                                                     \
    float4 av[8];                                                           \
    _Pragma("unroll")                                                       \
    for (int i = 0; i < 8; i++)                                             \
        av[i] = aptr[i] ? *(const float4*)(aptr[i] + k0 + kcA * 4)          \
                        : make_float4(0.f, 0.f, 0.f, 0.f);                  \
    float bv[8][4];                                                         \
    _Pragma("unroll")                                                       \
    for (int i = 0; i < 8; i++) {                                           \
        int kc = (i & 3) * 2 + (tid >> 7);                                  \
        const float* wb = ((i >> 2) ? wub : wgb)                            \
                        + (size_t)(k0 + kc * 4) * IDIM + nn;                \
        _Pragma("unroll")                                                   \
        for (int j = 0; j < 4; j++) bv[i][j] = ldg_ef(wb + (size_t)j * IDIM, pol); \
    }                                                                       \
    if (USED) { MBAR_WAIT(MB, PH); PH ^= 1; }                               \
    USED = 1;                                                               \
    _Pragma("unroll")                                                       \
    for (int i = 0; i < 8; i++) {                                           \
        int row = i * 32 + (tid >> 3);                                      \
        uint32_t o = SWZ128((uint32_t)(row * 128 + kcA * 16));              \
        uint4 v = { tf32r(av[i].x), tf32r(av[i].y),                         \
                    tf32r(av[i].z), tf32r(av[i].w) };                       \
        *(uint4*)(base + (AA) + o) = v;                                     \
    }                                                                       \
    _Pragma("unroll")                                                       \
    for (int i = 0; i < 8; i++) {                                           \
        int kc = (i & 3) * 2 + (tid >> 7);                                  \
        uint32_t o = SWZ128((uint32_t)(nn * 128 + kc * 16));                \
        uint4 v = { tf32r(bv[i][0]), tf32r(bv[i][1]),                       \
                    tf32r(bv[i][2]), tf32r(bv[i][3]) };                     \
        *(uint4*)(base + ((i >> 2) ? (ABU) : (ABG)) + o) = v;               \
    }                                                                       \
    __syncthreads();                                                        \
    if (tid < 32) {                                                         \
        FENCE_ASYNC();                                                      \
        if (elect_one()) {                                                  \
            uint64_t da0 = mk_desc(AA);                                     \
            uint64_t da1 = mk_desc((AA) + 128 * 128);                       \
            uint64_t dbg = mk_desc(ABG);                                    \
            uint64_t dbu = mk_desc(ABU);                                    \
            _Pragma("unroll")                                               \
            for (int s = 0; s < 4; s++) {                                   \
                uint32_t en = ((FIRSTC) && s == 0) ? 0u : 1u;               \
                uint64_t so = 2 * s;                                        \
                mma_tf32(tmem + 0,   da0 + so, dbg + so, en);               \
                mma_tf32(tmem + 128, da0 + so, dbu + so, en);               \
                mma_tf32(tmem + 256, da1 + so, dbg + so, en);               \
                mma_tf32(tmem + 384, da1 + so, dbu + so, en);               \
            }                                                               \
            TC_COMMIT(MB);                                                  \
        }                                                                   \
    }                                                                       \
} while (0)

    for (int row0 = 0; row0 < n; row0 += 256) {
        const float* aptr[8];
#pragma unroll
        for (int i = 0; i < 8; i++) {
            int gr = row0 + i * 32 + (tid >> 3);
            aptr[i] = (gr < n) ? x + (size_t)g_row_token[off + gr] * HID : nullptr;
        }
        for (int ch = 0; ch < HID / 32; ch += 2) {
            G1_CHUNK(ch,     aA0, aBG0, aBU0, mb0, ph0, used0, ch == 0);
            G1_CHUNK(ch + 1, aA1, aBG1, aBU1, mb1, ph1, used1, 0);
        }
        // last chunk (63) used buffer 1
        MBAR_WAIT(mb1, ph1); ph1 ^= 1; used1 = 0;
        TC_FENCE_AFTER();
        int rg = tid >> 7;
        uint32_t wo = ((uint32_t)((tid >> 5) & 3)) << 21;
        int grow = row0 + rg * 128 + (tid & 127);
        bool valid = grow < n;
        size_t orow = (size_t)(off + grow) * IDIM + ci * 128;
#pragma unroll
        for (int cb = 0; cb < 128; cb += 32) {
            uint32_t rgv[32], ruv[32];
            LDTM32(rgv, tmem + rg * 256 + cb + wo);
            LDTM32(ruv, tmem + rg * 256 + 128 + cb + wo);
            TC_WAIT_LD();
            if (valid) {
#pragma unroll
                for (int c = 0; c < 32; c += 4) {
                    uint4 o;
                    float gg, uu, a;
                    gg = __uint_as_float(rgv[c + 0]); uu = __uint_as_float(ruv[c + 0]);
                    a = (gg / (1.f + expf(-gg))) * uu; o.x = tf32r(a);
                    gg = __uint_as_float(rgv[c + 1]); uu = __uint_as_float(ruv[c + 1]);
                    a = (gg / (1.f + expf(-gg))) * uu; o.y = tf32r(a);
                    gg = __uint_as_float(rgv[c + 2]); uu = __uint_as_float(ruv[c + 2]);
                    a = (gg / (1.f + expf(-gg))) * uu; o.z = tf32r(a);
                    gg = __uint_as_float(rgv[c + 3]); uu = __uint_as_float(ruv[c + 3]);
                    a = (gg / (1.f + expf(-gg))) * uu; o.w = tf32r(a);
                    *(uint4*)(g_act + orow + cb + c) = o;
                }
            }
        }
        TC_FENCE_BEFORE();
        __syncthreads();
    }
#undef G1_CHUNK
    if (tid == 0) { MBAR_INVAL(mb0); MBAR_INVAL(mb1); }
    __syncthreads();
    if (tid < 32) { TC_RELINQ(); TC_DEALLOC(tmem, 512); }
#else
    // -------- SIMT fallback (R1 algorithm, 2 x 64-col halves) --------
    int e = blockIdx.y;
    int n = g_counts[e];
    if (n == 0) return;
    int off = g_offsets[e];
    int ci = blockIdx.x;
    __shared__ float As[16][128];
    __shared__ float Bgs[16][64];
    __shared__ float Bus[16][64];
    int tid = threadIdx.x;
    int tr = tid & 31, tc = tid >> 5;
    int lr = tid >> 1, lh = (tid & 1) * 8;
    int bkk = tid >> 4, bc = (tid & 15) * 4;
    for (int half = 0; half < 2; half++) {
        const float* wg = Wg + (size_t)e * HID * IDIM + ci * 128 + half * 64;
        const float* wu = Wu + (size_t)e * HID * IDIM + ci * 128 + half * 64;
        for (int row0 = 0; row0 < n; row0 += 128) {
            int rows = min(128, n - row0);
            const float* xrow = (lr < rows)
                ? (x + (size_t)g_row_token[off + row0 + lr] * HID) : nullptr;
            unsigned long long accg[4][4], accu[4][4];
#pragma unroll
            for (int r = 0; r < 4; r++)
#pragma unroll
                for (int p = 0; p < 4; p++) { accg[r][p] = 0ull; accu[r][p] = 0ull; }
            for (int k0 = 0; k0 < HID; k0 += 16) {
                float4 av0 = {0,0,0,0}, av1 = {0,0,0,0};
                if (xrow) {
                    av0 = *(const float4*)(xrow + k0 + lh);
                    av1 = *(const float4*)(xrow + k0 + lh + 4);
                }
                float4 bg = *(const float4*)(wg + (size_t)(k0 + bkk) * IDIM + bc);
                float4 bu = *(const float4*)(wu + (size_t)(k0 + bkk) * IDIM + bc);
                __syncthreads();
                As[lh + 0][lr] = av0.x; As[lh + 1][lr] = av0.y;
                As[lh + 2][lr] = av0.z; As[lh + 3][lr] = av0.w;
                As[lh + 4][lr] = av1.x; As[lh + 5][lr] = av1.y;
                As[lh + 6][lr] = av1.z; As[lh + 7][lr] = av1.w;
                *(float4*)&Bgs[bkk][bc] = bg;
                *(float4*)&Bus[bkk][bc] = bu;
                __syncthreads();
#pragma unroll
                for (int kk = 0; kk < 16; kk++) {
                    float4 av = *(const float4*)&As[kk][tr * 4];
                    ulonglong2 bg0 = *(const ulonglong2*)&Bgs[kk][tc * 8];
                    ulonglong2 bg1 = *(const ulonglong2*)&Bgs[kk][tc * 8 + 4];
                    ulonglong2 bu0 = *(const ulonglong2*)&Bus[kk][tc * 8];
                    ulonglong2 bu1 = *(const ulonglong2*)&Bus[kk][tc * 8 + 4];
                    unsigned long long aa[4] =
                        { splat2(av.x), splat2(av.y), splat2(av.z), splat2(av.w) };
#pragma unroll
                    for (int r = 0; r < 4; r++) {
                        fma2(accg[r][0], aa[r], bg0.x);
                        fma2(accg[r][1], aa[r], bg0.y);
                        fma2(accg[r][2], aa[r], bg1.x);
                        fma2(accg[r][3], aa[r], bg1.y);
                        fma2(accu[r][0], aa[r], bu0.x);
                        fma2(accu[r][1], aa[r], bu0.y);
                        fma2(accu[r][2], aa[r], bu1.x);
                        fma2(accu[r][3], aa[r], bu1.y);
                    }
                }
            }
#pragma unroll
            for (int r = 0; r < 4; r++) {
                int lrow = tr * 4 + r;
                if (lrow < rows) {
                    float* dst = g_act + (size_t)(off + row0 + lrow) * IDIM
                                 + ci * 128 + half * 64 + tc * 8;
#pragma unroll
                    for (int p = 0; p < 4; p++) {
                        float2 g = unpack2(accg[r][p]);
                        float2 u = unpack2(accu[r][p]);
                        dst[p * 2 + 0] = (g.x / (1.0f + expf(-g.x))) * u.x;
                        dst[p * 2 + 1] = (g.y / (1.0f + expf(-g.y))) * u.y;
                    }
                }
            }
        }
    }
#endif
}

// ---------------- grouped GEMM 2: down = act @ Wd ----------------------------
// grid (HID/128, NEXP), 256 threads, 2 CTAs/SM. Double-buffered mainloop.
__global__ __launch_bounds__(256, 2)
void gemm2_tc(const float* __restrict__ Wd) {
#if HAS_TC
    extern __shared__ char smem[];
    int e = blockIdx.y, ci = blockIdx.x;
    int n = g_counts[e];
    if (n == 0) return;
    int off = g_offsets[e];
    int tid = threadIdx.x;
    uint32_t sb = smem_u32(smem);
    uint32_t mb0 = sb + 8, mb1 = sb + 16;
    uint32_t aA0 = (sb + 1024 + 1023) & ~1023u;
    uint32_t aB0 = aA0 + 32768;
    uint32_t aA1 = aB0 + 16384;
    uint32_t aB1 = aA1 + 32768;
    char* base = smem - sb;
    uint64_t pol = mk_policy_ef();

    if (tid < 32) TC_ALLOC(sb, 256);
    if (tid == 0) { MBAR_INIT(mb0, 1); MBAR_INIT(mb1, 1); }
    __syncthreads();
    uint32_t tmem;
    asm volatile("ld.shared.b32 %0, [%1];" : "=r"(tmem) : "r"(sb));

    const float* wdb = Wd + (size_t)e * IDIM * HID + ci * 128;
    const int nn = tid & 127;
    const int kcA = tid & 7;
    uint32_t ph0 = 0, ph1 = 0;
    int used0 = 0, used1 = 0;

#define G2_CHUNK(CH, AA, AB, MB, PH, USED, FIRSTC) do {                     \
    int k0 = (CH) * 32;                                                     \
    uint4 av[8];                                                            \
    _Pragma("unroll")                                                       \
    for (int i = 0; i < 8; i++)                                             \
        av[i] = aptr[i] ? *(const uint4*)(aptr[i] + k0 + kcA * 4)           \
                        : make_uint4(0u, 0u, 0u, 0u);                       \
    float bv[4][4];                                                         \
    _Pragma("unroll")                                                       \
    for (int i = 0; i < 4; i++) {                                           \
        int kc = i * 2 + (tid >> 7);                                        \
        const float* wb = wdb + (size_t)(k0 + kc * 4) * HID + nn;           \
        _Pragma("unroll")                                                   \
        for (int j = 0; j < 4; j++) bv[i][j] = ldg_ef(wb + (size_t)j * HID, pol); \
    }                                                                       \
    if (USED) { MBAR_WAIT(MB, PH); PH ^= 1; }                               \
    USED = 1;                                                               \
    _Pragma("unroll")                                                       \
    for (int i = 0; i < 8; i++) {                                           \
        int row = i * 32 + (tid >> 3);                                      \
        uint32_t o = SWZ128((uint32_t)(row * 128 + kcA * 16));              \
        *(uint4*)(base + (AA) + o) = av[i];                                 \
    }                                                                       \
    _Pragma("unroll")                                                       \
    for (int i = 0; i < 4; i++) {                                           \
        int kc = i * 2 + (tid >> 7);                                        \
        uint32_t o = SWZ128((uint32_t)(nn * 128 + kc * 16));                \
        uint4 v = { tf32r(bv[i][0]), tf32r(bv[i][1]),                       \
                    tf32r(bv[i][2]), tf32r(bv[i][3]) };                     \
        *(uint4*)(base + (AB) + o) = v;                                     \
    }                                                                       \
    __syncthreads();                                                        \
    if (tid < 32) {                                                         \
        FENCE_ASYNC();                                                      \
        if (elect_one()) {                                                  \
            uint64_t da0 = mk_desc(AA);                                     \
            uint64_t da1 = mk_desc((AA) + 128 * 128);                       \
            uint64_t db  = mk_desc(AB);                                     \
            _Pragma("unroll")                                               \
            for (int s = 0; s < 4; s++) {                                   \
                uint32_t en = ((FIRSTC) && s == 0) ? 0u : 1u;               \
                uint64_t so = 2 * s;                                        \
                mma_tf32(tmem + 0,   da0 + so, db + so, en);                \
                mma_tf32(tmem + 128, da1 + so, db + so, en);                \
            }                                                               \
            TC_COMMIT(MB);                                                  \
        }                                                                   \
    }                                                                       \
} while (0)

    for (int row0 = 0; row0 < n; row0 += 256) {
        const float* aptr[8];
#pragma unroll
        for (int i = 0; i < 8; i++) {
            int gr = row0 + i * 32 + (tid >> 3);
            aptr[i] = (gr < n) ? g_act + (size_t)(off + gr) * IDIM : nullptr;
        }
        for (int ch = 0; ch < IDIM / 32; ch += 2) {
            G2_CHUNK(ch,     aA0, aB0, mb0, ph0, used0, ch == 0);
            G2_CHUNK(ch + 1, aA1, aB1, mb1, ph1, used1, 0);
        }
        // last chunk (23) used buffer 1
        MBAR_WAIT(mb1, ph1); ph1 ^= 1; used1 = 0;
        TC_FENCE_AFTER();
        int rg = tid >> 7;
        uint32_t wo = ((uint32_t)((tid >> 5) & 3)) << 21;
        int grow = row0 + rg * 128 + (tid & 127);
        bool valid = grow < n;
        size_t orow = (size_t)(off + grow) * HID + ci * 128;
#pragma unroll
        for (int cb = 0; cb < 128; cb += 32) {
            uint32_t dv[32];
            LDTM32(dv, tmem + rg * 128 + cb + wo);
            TC_WAIT_LD();
            if (valid) {
#pragma unroll
                for (int c = 0; c < 32; c += 4) {
                    uint4 o = { dv[c], dv[c + 1], dv[c + 2], dv[c + 3] };
                    *(uint4*)(g_down + orow + cb + c) = o;
                }
            }
        }
        TC_FENCE_BEFORE();
        __syncthreads();
    }
#undef G2_CHUNK
    if (tid == 0) { MBAR_INVAL(mb0); MBAR_INVAL(mb1); }
    __syncthreads();
    if (tid < 32) { TC_RELINQ(); TC_DEALLOC(tmem, 256); }
#else
    // -------- SIMT fallback --------
    int e = blockIdx.y;
    int n = g_counts[e];
    if (n == 0) return;
    int off = g_offsets[e];
    int ci = blockIdx.x;
    __shared__ float As[16][128];
    __shared__ float Bs[16][64];
    int tid = threadIdx.x;
    int tr = tid & 31, tc = tid >> 5;
    int lr = tid >> 1, lh = (tid & 1) * 8;
    int bkk = tid >> 4, bc = (tid & 15) * 4;
    for (int half = 0; half < 2; half++) {
        const float* wd = Wd + (size_t)e * IDIM * HID + ci * 128 + half * 64;
        for (int row0 = 0; row0 < n; row0 += 128) {
            int rows = min(128, n - row0);
            const float* arow = (lr < rows)
                ? (g_act + (size_t)(off + row0 + lr) * IDIM) : nullptr;
            unsigned long long acc[4][4];
#pragma unroll
            for (int r = 0; r < 4; r++)
#pragma unroll
                for (int p = 0; p < 4; p++) acc[r][p] = 0ull;
            for (int k0 = 0; k0 < IDIM; k0 += 16) {
                float4 av0 = {0,0,0,0}, av1 = {0,0,0,0};
                if (arow) {
                    av0 = *(const float4*)(arow + k0 + lh);
                    av1 = *(const float4*)(arow + k0 + lh + 4);
                }
                float4 bd = *(const float4*)(wd + (size_t)(k0 + bkk) * HID + bc);
                __syncthreads();
                As[lh + 0][lr] = av0.x; As[lh + 1][lr] = av0.y;
                As[lh + 2][lr] = av0.z; As[lh + 3][lr] = av0.w;
                As[lh + 4][lr] = av1.x; As[lh + 5][lr] = av1.y;
                As[lh + 6][lr] = av1.z; As[lh + 7][lr] = av1.w;
                *(float4*)&Bs[bkk][bc] = bd;
                __syncthreads();
#pragma unroll
                for (int kk = 0; kk < 16; kk++) {
                    float4 av = *(const float4*)&As[kk][tr * 4];
                    ulonglong2 b0 = *(const ulonglong2*)&Bs[kk][tc * 8];
                    ulonglong2 b1 = *(const ulonglong2*)&Bs[kk][tc * 8 + 4];
                    unsigned long long aa[4] =
                        { splat2(av.x), splat2(av.y), splat2(av.z), splat2(av.w) };
#pragma unroll
                    for (int r = 0; r < 4; r++) {
                        fma2(acc[r][0], aa[r], b0.x);
                        fma2(acc[r][1], aa[r], b0.y);
                        fma2(acc[r][2], aa[r], b1.x);
                        fma2(acc[r][3], aa[r], b1.y);
                    }
                }
            }
#pragma unroll
            for (int r = 0; r < 4; r++) {
                int lrow = tr * 4 + r;
                if (lrow < rows) {
                    float* dst = g_down + (size_t)(off + row0 + lrow) * HID
                                 + ci * 128 + half * 64 + tc * 8;
                    unsigned long long* dq = (unsigned long long*)dst;
#pragma unroll
                    for (int p = 0; p < 4; p++) dq[p] = acc[r][p];
                }
            }
        }
    }
#endif
}

// ---------------- combine ----------------------------------------------------
__global__ __launch_bounds__(512)
void combine_kernel(float* __restrict__ out) {
    int t = blockIdx.x;
    int h4 = threadIdx.x;
    __shared__ float sw[TOPK];
    __shared__ int   sp[TOPK];
    if (threadIdx.x < TOPK) {
        sw[threadIdx.x] = g_wt[t * TOPK + threadIdx.x];
        sp[threadIdx.x] = g_pos_of[t * TOPK + threadIdx.x];
    }
    __syncthreads();
    float4 acc = make_float4(0.f, 0.f, 0.f, 0.f);
#pragma unroll
    for (int k = 0; k < TOPK; k++) {
        float w = sw[k];
        float4 v = ((const float4*)(g_down + (size_t)sp[k] * HID))[h4];
        acc.x += w * v.x; acc.y += w * v.y; acc.z += w * v.z; acc.w += w * v.w;
    }
    ((float4*)(out + (size_t)t * HID))[h4] = acc;
}

// ---------------- launch -----------------------------------------------------
extern "C" void kernel_launch(void* const* d_in, const int* in_sizes, int n_in,
                              void* d_out, int out_size) {
    const float* x  = (const float*)d_in[0];
    const float* gw = (const float*)d_in[1];
    const float* Wg = (const float*)d_in[2];
    const float* Wu = (const float*)d_in[3];
    const float* Wd = (const float*)d_in[4];
    float* out = (float*)d_out;

    cudaFuncSetAttribute(gemm1_tc, cudaFuncAttributeMaxDynamicSharedMemorySize, SM1_TOT);
    cudaFuncSetAttribute(gemm2_tc, cudaFuncAttributeMaxDynamicSharedMemorySize, SM2_TOT);

    zero_kernel<<<1, 64>>>();
    router_kernel<<<TOKS / 16, 256>>>(x, gw);
    scatter2_kernel<<<1, 512>>>();
    gemm1_tc<<<dim3(IDIM / 128, NEXP), 256, SM1_TOT>>>(x, Wg, Wu);
    gemm2_tc<<<dim3(HID / 128, NEXP), 256, SM2_TOT>>>(Wd);
    combine_kernel<<<TOKS, 512>>>(out);
}

// round 16
// speedup vs baseline: 1.3246x; 1.1584x over previous
#include <cuda_runtime.h>
#include <cstdint>
#include <math.h>

#define TOKS 2048
#define HID  2048
#define NEXP 64
#define IDIM 768
#define TOPK 8
#define NROWS 16384   // TOKS*TOPK

// ---- arch-feature gate: tcgen05 only exists in the sm_103a-specific pass ----
#define HAS_TC 0
#ifdef __CUDA_ARCH_FEAT_SM103_ALL
#undef HAS_TC
#define HAS_TC 1
#endif
#ifdef __CUDA_ARCH_HAS_FEATURE__
#if __CUDA_ARCH_HAS_FEATURE__(SM103_ALL)
#undef HAS_TC
#define HAS_TC 1
#endif
#endif

// ---------------- scratch (device globals; no allocation allowed) ----------
__device__ int   g_counts[NEXP];
__device__ int   g_offsets[NEXP + 1];
__device__ int   g_sel[NROWS];
__device__ float g_wt[NROWS];
__device__ int   g_row_token[NROWS];
__device__ int   g_pos_of[NROWS];
__device__ float g_act[(size_t)NROWS * IDIM];
__device__ float g_down[(size_t)NROWS * HID];

// ---------------- generic helpers -------------------------------------------
__device__ __forceinline__ uint32_t smem_u32(const void* p) {
    uint32_t a;
    asm("{ .reg .u64 t; cvta.to.shared.u64 t, %1; cvt.u32.u64 %0, t; }"
        : "=r"(a) : "l"(p));
    return a;
}
__device__ __forceinline__ uint32_t tf32r(float x) {
    uint32_t u;
    asm("cvt.rna.tf32.f32 %0, %1;" : "=r"(u) : "f"(x));
    return u;
}
__device__ __forceinline__ uint64_t mk_policy_ef() {
    uint64_t pol;
    asm("createpolicy.fractional.L2::evict_first.b64 %0, 1.0;" : "=l"(pol));
    return pol;
}
__device__ __forceinline__ float ldg_ef(const float* p, uint64_t pol) {
    float v;
    asm volatile("ld.global.nc.L2::cache_hint.f32 %0, [%1], %2;"
                 : "=f"(v) : "l"(p), "l"(pol));
    return v;
}
#define SWZ128(o) ((o) ^ (((o) >> 3) & 0x70))

// packed f32x2 (family-wide on sm_10x, fine for compute_103)
__device__ __forceinline__ void fma2(unsigned long long& d, unsigned long long a,
                                     unsigned long long b) {
    asm("fma.rn.f32x2 %0, %1, %2, %0;" : "+l"(d) : "l"(a), "l"(b));
}
__device__ __forceinline__ unsigned long long splat2(float a) {
    unsigned long long r;
    unsigned int u = __float_as_uint(a);
    asm("mov.b64 %0, {%1, %1};" : "=l"(r) : "r"(u));
    return r;
}
__device__ __forceinline__ float2 unpack2(unsigned long long v) {
    unsigned int lo, hi;
    asm("mov.b64 {%0, %1}, %2;" : "=r"(lo), "=r"(hi) : "l"(v));
    return make_float2(__uint_as_float(lo), __uint_as_float(hi));
}

#if HAS_TC
// ---------------- tcgen05 helpers (guarded) ----------------------------------
__device__ __forceinline__ uint32_t elect_one() {
    uint32_t p;
    asm volatile("{\n\t.reg .pred p;\n\telect.sync _|p, 0xFFFFFFFF;\n\t"
                 "selp.b32 %0, 1, 0, p;\n\t}" : "=r"(p));
    return p;
}
#define MBAR_INIT(a, c) \
    asm volatile("mbarrier.init.shared.b64 [%0], %1;" :: "r"(a), "r"(c) : "memory")
#define MBAR_INVAL(a) \
    asm volatile("mbarrier.inval.shared.b64 [%0];" :: "r"(a) : "memory")
#define MBAR_WAIT(a, par) do {                                              \
    uint32_t _m = (a), _p = (par), _d;                                      \
    asm volatile("{\n\t.reg .pred p;\n\t"                                   \
        "mbarrier.try_wait.parity.acquire.cta.shared::cta.b64 p, [%1], %2;\n\t" \
        "selp.b32 %0, 1, 0, p;\n\t}" : "=r"(_d) : "r"(_m), "r"(_p) : "memory"); \
    if (!_d) {                                                              \
        asm volatile("{\n\t.reg .pred P1;\n\t"                              \
            "W%=:\n\t"                                                       \
            "mbarrier.try_wait.parity.acquire.cta.shared::cta.b64 P1, [%0], %1, 0x989680;\n\t" \
            "@P1 bra.uni D%=;\n\tbra.uni W%=;\n\tD%=:\n\t}"                  \
            :: "r"(_m), "r"(_p) : "memory");                                \
    }                                                                       \
} while (0)

#define TC_ALLOC(sa, n) \
    asm volatile("tcgen05.alloc.cta_group::1.sync.aligned.shared::cta.b32 [%0], %1;" \
                 :: "r"(sa), "r"((uint32_t)(n)) : "memory")
#define TC_DEALLOC(t, n) \
    asm volatile("tcgen05.dealloc.cta_group::1.sync.aligned.b32 %0, %1;" \
                 :: "r"(t), "r"((uint32_t)(n)))
#define TC_RELINQ() \
    asm volatile("tcgen05.relinquish_alloc_permit.cta_group::1.sync.aligned;")
#define TC_COMMIT(mb) \
    asm volatile("tcgen05.commit.cta_group::1.mbarrier::arrive::one.shared::cluster.b64 [%0];" \
                 :: "r"(mb) : "memory")
#define TC_FENCE_BEFORE() asm volatile("tcgen05.fence::before_thread_sync;" ::: "memory")
#define TC_FENCE_AFTER()  asm volatile("tcgen05.fence::after_thread_sync;" ::: "memory")
#define TC_WAIT_LD()      asm volatile("tcgen05.wait::ld.sync.aligned;" ::: "memory")
#define FENCE_ASYNC()     asm volatile("fence.proxy.async.shared::cta;" ::: "memory")

#define LDTM32(r, a)                                                         \
    asm volatile("tcgen05.ld.sync.aligned.32x32b.x32.b32 "                   \
        "{%0,%1,%2,%3,%4,%5,%6,%7,%8,%9,%10,%11,%12,%13,%14,%15,"            \
        "%16,%17,%18,%19,%20,%21,%22,%23,%24,%25,%26,%27,%28,%29,%30,%31}, [%32];" \
        : "=r"((r)[0]),"=r"((r)[1]),"=r"((r)[2]),"=r"((r)[3]),               \
          "=r"((r)[4]),"=r"((r)[5]),"=r"((r)[6]),"=r"((r)[7]),               \
          "=r"((r)[8]),"=r"((r)[9]),"=r"((r)[10]),"=r"((r)[11]),             \
          "=r"((r)[12]),"=r"((r)[13]),"=r"((r)[14]),"=r"((r)[15]),           \
          "=r"((r)[16]),"=r"((r)[17]),"=r"((r)[18]),"=r"((r)[19]),           \
          "=r"((r)[20]),"=r"((r)[21]),"=r"((r)[22]),"=r"((r)[23]),           \
          "=r"((r)[24]),"=r"((r)[25]),"=r"((r)[26]),"=r"((r)[27]),           \
          "=r"((r)[28]),"=r"((r)[29]),"=r"((r)[30]),"=r"((r)[31])            \
        : "r"(a))

__device__ __forceinline__ uint64_t mk_desc(uint32_t addr) {
    const uint64_t base = (uint64_t(2) << 61) | (uint64_t(1) << 46)
                        | (uint64_t(64) << 32) | (uint64_t(1) << 16);
    return base | ((uint64_t)(addr >> 4) & 0x3FFF);
}
#define IDESC_TF32_128 ((1u << 4) | (2u << 7) | (2u << 10) | (16u << 17) | (8u << 24))
__device__ __forceinline__ void mma_tf32(uint32_t d, uint64_t a, uint64_t b,
                                         uint32_t en) {
    asm volatile("{\n\t.reg .pred p;\n\tsetp.ne.u32 p, %5, 0;\n\t"
        "tcgen05.mma.cta_group::1.kind::tf32 [%0], %1, %2, %3, {%4,%4,%4,%4}, p;\n\t}"
        :: "r"(d), "l"(a), "l"(b), "r"(IDESC_TF32_128), "r"(0u), "r"(en)
        : "memory");
}
#endif // HAS_TC

// ---------------- setup kernels ----------------------------------------------
__global__ void zero_kernel() {
    int t = threadIdx.x;
    if (t < NEXP) g_counts[t] = 0;
}

// merged scan + scatter
__global__ __launch_bounds__(512)
void scatter2_kernel() {
    __shared__ int soff[NEXP];
    __shared__ int scur[NEXP];
    int tid = threadIdx.x;
    if (tid == 0) {
        int s = 0;
        for (int e = 0; e < NEXP; e++) {
            soff[e] = s; g_offsets[e] = s; s += g_counts[e];
        }
        g_offsets[NEXP] = s;
    }
    if (tid < NEXP) scur[tid] = 0;
    __syncthreads();
#pragma unroll
    for (int it = 0; it < NROWS / 512; it++) {
        int i = it * 512 + tid;
        int e = g_sel[i];
        int p = soff[e] + atomicAdd(&scur[e], 1);
        g_row_token[p] = i >> 3;
        g_pos_of[i] = p;
    }
}

// ---------------- router -----------------------------------------------------
__global__ void router_kernel(const float* __restrict__ x,
                              const float* __restrict__ gw) {
    __shared__ float xs[16][64];
    __shared__ float gws[64][64];
    __shared__ float lg[16][64];
    int tid = threadIdx.x;
    int t0 = blockIdx.x * 16;
    int tok = tid >> 4, eg = tid & 15;
    float a0 = 0.f, a1 = 0.f, a2 = 0.f, a3 = 0.f;
    for (int h0 = 0; h0 < HID; h0 += 64) {
#pragma unroll
        for (int i = 0; i < 4; i++) {
            int idx = i * 256 + tid;
            int row = idx >> 4, col = (idx & 15) * 4;
            *(float4*)&gws[row][col] =
                *(const float4*)(gw + (size_t)(h0 + row) * NEXP + col);
        }
        {
            int row = tid >> 4, col = (tid & 15) * 4;
            *(float4*)&xs[row][col] =
                *(const float4*)(x + (size_t)(t0 + row) * HID + h0 + col);
        }
        __syncthreads();
#pragma unroll 8
        for (int hh = 0; hh < 64; hh++) {
            float xv = xs[tok][hh];
            float4 g4 = *(const float4*)&gws[hh][eg * 4];
            a0 += xv * g4.x; a1 += xv * g4.y; a2 += xv * g4.z; a3 += xv * g4.w;
        }
        __syncthreads();
    }
    lg[tok][eg * 4 + 0] = a0; lg[tok][eg * 4 + 1] = a1;
    lg[tok][eg * 4 + 2] = a2; lg[tok][eg * 4 + 3] = a3;
    __syncthreads();
    if (tid < 16) {
        int t = t0 + tid;
        float vals[TOPK]; int sel[TOPK];
#pragma unroll
        for (int k = 0; k < TOPK; k++) {
            float best = -3.4e38f; int bi = 0;
            for (int e2 = 0; e2 < NEXP; e2++) {
                float v = lg[tid][e2];
                if (v > best) { best = v; bi = e2; }
            }
            vals[k] = best; sel[k] = bi;
            lg[tid][bi] = -3.4e38f;
        }
        float m = vals[0], ex[TOPK], s = 0.f;
#pragma unroll
        for (int k = 0; k < TOPK; k++) { ex[k] = expf(vals[k] - m); s += ex[k]; }
        float inv = 1.0f / s;
#pragma unroll
        for (int k = 0; k < TOPK; k++) {
            g_sel[t * TOPK + k] = sel[k];
            g_wt[t * TOPK + k] = ex[k] * inv;
            atomicAdd(&g_counts[sel[k]], 1);
        }
    }
}

// dynamic smem: header 2KB + double-buffered tiles
#define SM1_TOT (2048 + 2 * (32768 + 16384 + 16384))   // 133120
#define SM2_TOT (2048 + 2 * (32768 + 16384))           // 100352

// ---------------- grouped GEMM 1: act = silu(x@Wg)*(x@Wu) --------------------
// grid (IDIM/128, NEXP), 512 threads (16 warps). Double-buffered mainloop.
__global__ __launch_bounds__(512)
void gemm1_tc(const float* __restrict__ x,
              const float* __restrict__ Wg,
              const float* __restrict__ Wu) {
#if HAS_TC
    extern __shared__ char smem[];
    int e = blockIdx.y, ci = blockIdx.x;
    int n = g_counts[e];
    if (n == 0) return;
    int off = g_offsets[e];
    int tid = threadIdx.x;
    uint32_t sb = smem_u32(smem);
    uint32_t mb0 = sb + 8, mb1 = sb + 16;
    uint32_t aA0 = (sb + 1024 + 1023) & ~1023u;
    uint32_t aBG0 = aA0 + 32768, aBU0 = aBG0 + 16384;
    uint32_t aA1 = aBU0 + 16384;
    uint32_t aBG1 = aA1 + 32768, aBU1 = aBG1 + 16384;
    char* base = smem - sb;     // char* such that base + smem_addr = generic ptr
    uint64_t pol = mk_policy_ef();

    if (tid < 32) TC_ALLOC(sb, 512);
    if (tid == 0) { MBAR_INIT(mb0, 1); MBAR_INIT(mb1, 1); }
    __syncthreads();
    uint32_t tmem;
    asm volatile("ld.shared.b32 %0, [%1];" : "=r"(tmem) : "r"(sb));

    const float* wgb = Wg + (size_t)e * HID * IDIM + ci * 128;
    const float* wub = Wu + (size_t)e * HID * IDIM + ci * 128;
    const int nn  = tid & 127;          // B n-row
    const int quad = tid >> 7;          // 0..3: (matrix, k-quad)
    const int kcg = (quad & 1) * 4;     // this thread's 4 k-cells: kcg..kcg+3
    const float* wmb = (quad >> 1) ? wub : wgb;
    const int kcA = tid & 7;            // A k-cell
    uint32_t ph0 = 0, ph1 = 0;
    int used0 = 0, used1 = 0;

#define G1_CHUNK(CH, AA, ABG, ABU, MB, PH, USED, FIRSTC) do {               \
    int k0 = (CH) * 32;                                                     \
    float4 av[4];                                                           \
    _Pragma("unroll")                                                       \
    for (int i = 0; i < 4; i++)                                             \
        av[i] = aptr[i] ? *(const float4*)(aptr[i] + k0 + kcA * 4)          \
                        : make_float4(0.f, 0.f, 0.f, 0.f);                  \
    float bv[4][4];                                                         \
    _Pragma("unroll")                                                       \
    for (int c = 0; c < 4; c++) {                                           \
        const float* wb = wmb + (size_t)(k0 + (kcg + c) * 4) * IDIM + nn;   \
        _Pragma("unroll")                                                   \
        for (int j = 0; j < 4; j++) bv[c][j] = ldg_ef(wb + (size_t)j * IDIM, pol); \
    }                                                                       \
    if (USED) { MBAR_WAIT(MB, PH); PH ^= 1; }                               \
    USED = 1;                                                               \
    _Pragma("unroll")                                                       \
    for (int i = 0; i < 4; i++) {                                           \
        int row = i * 64 + (tid >> 3);                                      \
        uint32_t o = SWZ128((uint32_t)(row * 128 + kcA * 16));              \
        uint4 v = { tf32r(av[i].x), tf32r(av[i].y),                         \
                    tf32r(av[i].z), tf32r(av[i].w) };                       \
        *(uint4*)(base + (AA) + o) = v;                                     \
    }                                                                       \
    {                                                                       \
        char* bbase = base + ((quad >> 1) ? (ABU) : (ABG));                 \
        _Pragma("unroll")                                                   \
        for (int c = 0; c < 4; c++) {                                       \
            uint32_t o = SWZ128((uint32_t)(nn * 128 + (kcg + c) * 16));     \
            uint4 v = { tf32r(bv[c][0]), tf32r(bv[c][1]),                   \
                        tf32r(bv[c][2]), tf32r(bv[c][3]) };                 \
            *(uint4*)(bbase + o) = v;                                       \
        }                                                                   \
    }                                                                       \
    __syncthreads();                                                        \
    if (tid < 32) {                                                         \
        FENCE_ASYNC();                                                      \
        if (elect_one()) {                                                  \
            uint64_t da0 = mk_desc(AA);                                     \
            uint64_t da1 = mk_desc((AA) + 128 * 128);                       \
            uint64_t dbg = mk_desc(ABG);                                    \
            uint64_t dbu = mk_desc(ABU);                                    \
            _Pragma("unroll")                                               \
            for (int s = 0; s < 4; s++) {                                   \
                uint32_t en = ((FIRSTC) && s == 0) ? 0u : 1u;               \
                uint64_t so = 2 * s;                                        \
                mma_tf32(tmem + 0,   da0 + so, dbg + so, en);               \
                mma_tf32(tmem + 128, da0 + so, dbu + so, en);               \
                mma_tf32(tmem + 256, da1 + so, dbg + so, en);               \
                mma_tf32(tmem + 384, da1 + so, dbu + so, en);               \
            }                                                               \
            TC_COMMIT(MB);                                                  \
        }                                                                   \
    }                                                                       \
} while (0)

    for (int row0 = 0; row0 < n; row0 += 256) {
        const float* aptr[4];
#pragma unroll
        for (int i = 0; i < 4; i++) {
            int gr = row0 + i * 64 + (tid >> 3);
            aptr[i] = (gr < n) ? x + (size_t)g_row_token[off + gr] * HID : nullptr;
        }
        for (int ch = 0; ch < HID / 32; ch += 2) {
            G1_CHUNK(ch,     aA0, aBG0, aBU0, mb0, ph0, used0, ch == 0);
            G1_CHUNK(ch + 1, aA1, aBG1, aBU1, mb1, ph1, used1, 0);
        }
        // last chunk (63) used buffer 1
        MBAR_WAIT(mb1, ph1); ph1 ^= 1; used1 = 0;
        TC_FENCE_AFTER();
        // 16 warps: w -> (rg = (w>>2)&1, colhalf = w>>3), lanes via (w&3)
        int w = tid >> 5;
        int rg = (w >> 2) & 1;
        int ch2 = w >> 3;
        uint32_t wo = ((uint32_t)(w & 3)) << 21;
        int grow = row0 + rg * 128 + (tid & 127);
        bool valid = grow < n;
        size_t orow = (size_t)(off + grow) * IDIM + ci * 128;
#pragma unroll
        for (int cb2 = 0; cb2 < 2; cb2++) {
            int cb = ch2 * 64 + cb2 * 32;
            uint32_t rgv[32], ruv[32];
            LDTM32(rgv, tmem + rg * 256 + cb + wo);
            LDTM32(ruv, tmem + rg * 256 + 128 + cb + wo);
            TC_WAIT_LD();
            if (valid) {
#pragma unroll
                for (int c = 0; c < 32; c += 4) {
                    uint4 o;
                    float gg, uu, a;
                    gg = __uint_as_float(rgv[c + 0]); uu = __uint_as_float(ruv[c + 0]);
                    a = (gg / (1.f + expf(-gg))) * uu; o.x = tf32r(a);
                    gg = __uint_as_float(rgv[c + 1]); uu = __uint_as_float(ruv[c + 1]);
                    a = (gg / (1.f + expf(-gg))) * uu; o.y = tf32r(a);
                    gg = __uint_as_float(rgv[c + 2]); uu = __uint_as_float(ruv[c + 2]);
                    a = (gg / (1.f + expf(-gg))) * uu; o.z = tf32r(a);
                    gg = __uint_as_float(rgv[c + 3]); uu = __uint_as_float(ruv[c + 3]);
                    a = (gg / (1.f + expf(-gg))) * uu; o.w = tf32r(a);
                    *(uint4*)(g_act + orow + cb + c) = o;
                }
            }
        }
        TC_FENCE_BEFORE();
        __syncthreads();
    }
#undef G1_CHUNK
    if (tid == 0) { MBAR_INVAL(mb0); MBAR_INVAL(mb1); }
    __syncthreads();
    if (tid < 32) { TC_RELINQ(); TC_DEALLOC(tmem, 512); }
#else
    // -------- SIMT fallback (guarded for 512-thread launch) --------
    int e = blockIdx.y;
    int n = g_counts[e];
    if (n == 0) return;
    int off = g_offsets[e];
    int ci = blockIdx.x;
    __shared__ float As[16][128];
    __shared__ float Bgs[16][64];
    __shared__ float Bus[16][64];
    int tid = threadIdx.x;
    bool act = tid < 256;
    int tr = tid & 31, tc = (tid >> 5) & 7;
    int lr = (tid >> 1) & 127, lh = (tid & 1) * 8;
    int bkk = (tid >> 4) & 15, bc = (tid & 15) * 4;
    for (int half = 0; half < 2; half++) {
        const float* wg = Wg + (size_t)e * HID * IDIM + ci * 128 + half * 64;
        const float* wu = Wu + (size_t)e * HID * IDIM + ci * 128 + half * 64;
        for (int row0 = 0; row0 < n; row0 += 128) {
            int rows = min(128, n - row0);
            const float* xrow = (act && lr < rows)
                ? (x + (size_t)g_row_token[off + row0 + lr] * HID) : nullptr;
            unsigned long long accg[4][4], accu[4][4];
#pragma unroll
            for (int r = 0; r < 4; r++)
#pragma unroll
                for (int p = 0; p < 4; p++) { accg[r][p] = 0ull; accu[r][p] = 0ull; }
            for (int k0 = 0; k0 < HID; k0 += 16) {
                float4 av0 = {0,0,0,0}, av1 = {0,0,0,0};
                float4 bg = {0,0,0,0}, bu = {0,0,0,0};
                if (xrow) {
                    av0 = *(const float4*)(xrow + k0 + lh);
                    av1 = *(const float4*)(xrow + k0 + lh + 4);
                }
                if (act) {
                    bg = *(const float4*)(wg + (size_t)(k0 + bkk) * IDIM + bc);
                    bu = *(const float4*)(wu + (size_t)(k0 + bkk) * IDIM + bc);
                }
                __syncthreads();
                if (act) {
                    As[lh + 0][lr] = av0.x; As[lh + 1][lr] = av0.y;
                    As[lh + 2][lr] = av0.z; As[lh + 3][lr] = av0.w;
                    As[lh + 4][lr] = av1.x; As[lh + 5][lr] = av1.y;
                    As[lh + 6][lr] = av1.z; As[lh + 7][lr] = av1.w;
                    *(float4*)&Bgs[bkk][bc] = bg;
                    *(float4*)&Bus[bkk][bc] = bu;
                }
                __syncthreads();
                if (act) {
#pragma unroll
                    for (int kk = 0; kk < 16; kk++) {
                        float4 av = *(const float4*)&As[kk][tr * 4];
                        ulonglong2 bg0 = *(const ulonglong2*)&Bgs[kk][tc * 8];
                        ulonglong2 bg1 = *(const ulonglong2*)&Bgs[kk][tc * 8 + 4];
                        ulonglong2 bu0 = *(const ulonglong2*)&Bus[kk][tc * 8];
                        ulonglong2 bu1 = *(const ulonglong2*)&Bus[kk][tc * 8 + 4];
                        unsigned long long aa[4] =
                            { splat2(av.x), splat2(av.y), splat2(av.z), splat2(av.w) };
#pragma unroll
                        for (int r = 0; r < 4; r++) {
                            fma2(accg[r][0], aa[r], bg0.x);
                            fma2(accg[r][1], aa[r], bg0.y);
                            fma2(accg[r][2], aa[r], bg1.x);
                            fma2(accg[r][3], aa[r], bg1.y);
                            fma2(accu[r][0], aa[r], bu0.x);
                            fma2(accu[r][1], aa[r], bu0.y);
                            fma2(accu[r][2], aa[r], bu1.x);
                            fma2(accu[r][3], aa[r], bu1.y);
                        }
                    }
                }
            }
            if (act) {
#pragma unroll
                for (int r = 0; r < 4; r++) {
                    int lrow = tr * 4 + r;
                    if (lrow < rows) {
                        float* dst = g_act + (size_t)(off + row0 + lrow) * IDIM
                                     + ci * 128 + half * 64 + tc * 8;
#pragma unroll
                        for (int p = 0; p < 4; p++) {
                            float2 g = unpack2(accg[r][p]);
                            float2 u = unpack2(accu[r][p]);
                            dst[p * 2 + 0] = (g.x / (1.0f + expf(-g.x))) * u.x;
                            dst[p * 2 + 1] = (g.y / (1.0f + expf(-g.y))) * u.y;
                        }
                    }
                }
            }
        }
    }
#endif
}

// ---------------- grouped GEMM 2: down = act @ Wd ----------------------------
// grid (HID/128, NEXP), 256 threads, 2 CTAs/SM. Double-buffered mainloop.
__global__ __launch_bounds__(256, 2)
void gemm2_tc(const float* __restrict__ Wd) {
#if HAS_TC
    extern __shared__ char smem[];
    int e = blockIdx.y, ci = blockIdx.x;
    int n = g_counts[e];
    if (n == 0) return;
    int off = g_offsets[e];
    int tid = threadIdx.x;
    uint32_t sb = smem_u32(smem);
    uint32_t mb0 = sb + 8, mb1 = sb + 16;
    uint32_t aA0 = (sb + 1024 + 1023) & ~1023u;
    uint32_t aB0 = aA0 + 32768;
    uint32_t aA1 = aB0 + 16384;
    uint32_t aB1 = aA1 + 32768;
    char* base = smem - sb;
    uint64_t pol = mk_policy_ef();

    if (tid < 32) TC_ALLOC(sb, 256);
    if (tid == 0) { MBAR_INIT(mb0, 1); MBAR_INIT(mb1, 1); }
    __syncthreads();
    uint32_t tmem;
    asm volatile("ld.shared.b32 %0, [%1];" : "=r"(tmem) : "r"(sb));

    const float* wdb = Wd + (size_t)e * IDIM * HID + ci * 128;
    const int nn = tid & 127;
    const int kcA = tid & 7;
    uint32_t ph0 = 0, ph1 = 0;
    int used0 = 0, used1 = 0;

#define G2_CHUNK(CH, AA, AB, MB, PH, USED, FIRSTC) do {                     \
    int k0 = (CH) * 32;                                                     \
    uint4 av[8];                                                            \
    _Pragma("unroll")                                                       \
    for (int i = 0; i < 8; i++)                                             \
        av[i] = aptr[i] ? *(const uint4*)(aptr[i] + k0 + kcA * 4)           \
                        : make_uint4(0u, 0u, 0u, 0u);                       \
    float bv[4][4];                                                         \
    _Pragma("unroll")                                                       \
    for (int i = 0; i < 4; i++) {                                           \
        int kc = i * 2 + (tid >> 7);                                        \
        const float* wb = wdb + (size_t)(k0 + kc * 4) * HID + nn;           \
        _Pragma("unroll")                                                   \
        for (int j = 0; j < 4; j++) bv[i][j] = ldg_ef(wb + (size_t)j * HID, pol); \
    }                                                                       \
    if (USED) { MBAR_WAIT(MB, PH); PH ^= 1; }                               \
    USED = 1;                                                               \
    _Pragma("unroll")                                                       \
    for (int i = 0; i < 8; i++) {                                           \
        int row = i * 32 + (tid >> 3);                                      \
        uint32_t o = SWZ128((uint32_t)(row * 128 + kcA * 16));              \
        *(uint4*)(base + (AA) + o) = av[i];                                 \
    }                                                                       \
    _Pragma("unroll")                                                       \
    for (int i = 0; i < 4; i++) {                                           \
        int kc = i * 2 + (tid >> 7);                                        \
        uint32_t o = SWZ128((uint32_t)(nn * 128 + kc * 16));                \
        uint4 v = { tf32r(bv[i][0]), tf32r(bv[i][1]),                       \
                    tf32r(bv[i][2]), tf32r(bv[i][3]) };                     \
        *(uint4*)(base + (AB) + o) = v;                                     \
    }                                                                       \
    __syncthreads();                                                        \
    if (tid < 32) {                                                         \
        FENCE_ASYNC();                                                      \
        if (elect_one()) {                                                  \
            uint64_t da0 = mk_desc(AA);                                     \
            uint64_t da1 = mk_desc((AA) + 128 * 128);                       \
            uint64_t db  = mk_desc(AB);                                     \
            _Pragma("unroll")                                               \
            for (int s = 0; s < 4; s++) {                                   \
                uint32_t en = ((FIRSTC) && s == 0) ? 0u : 1u;               \
                uint64_t so = 2 * s;                                        \
                mma_tf32(tmem + 0,   da0 + so, db + so, en);                \
                mma_tf32(tmem + 128, da1 + so, db + so, en);                \
            }                                                               \
            TC_COMMIT(MB);                                                  \
        }                                                                   \
    }                                                                       \
} while (0)

    for (int row0 = 0; row0 < n; row0 += 256) {
        const float* aptr[8];
#pragma unroll
        for (int i = 0; i < 8; i++) {
            int gr = row0 + i * 32 + (tid >> 3);
            aptr[i] = (gr < n) ? g_act + (size_t)(off + gr) * IDIM : nullptr;
        }
        for (int ch = 0; ch < IDIM / 32; ch += 2) {
            G2_CHUNK(ch,     aA0, aB0, mb0, ph0, used0, ch == 0);
            G2_CHUNK(ch + 1, aA1, aB1, mb1, ph1, used1, 0);
        }
        // last chunk (23) used buffer 1
        MBAR_WAIT(mb1, ph1); ph1 ^= 1; used1 = 0;
        TC_FENCE_AFTER();
        int rg = tid >> 7;
        uint32_t wo = ((uint32_t)((tid >> 5) & 3)) << 21;
        int grow = row0 + rg * 128 + (tid & 127);
        bool valid = grow < n;
        size_t orow = (size_t)(off + grow) * HID + ci * 128;
#pragma unroll
        for (int cb = 0; cb < 128; cb += 32) {
            uint32_t dv[32];
            LDTM32(dv, tmem + rg * 128 + cb + wo);
            TC_WAIT_LD();
            if (valid) {
#pragma unroll
                for (int c = 0; c < 32; c += 4) {
                    uint4 o = { dv[c], dv[c + 1], dv[c + 2], dv[c + 3] };
                    *(uint4*)(g_down + orow + cb + c) = o;
                }
            }
        }
        TC_FENCE_BEFORE();
        __syncthreads();
    }
#undef G2_CHUNK
    if (tid == 0) { MBAR_INVAL(mb0); MBAR_INVAL(mb1); }
    __syncthreads();
    if (tid < 32) { TC_RELINQ(); TC_DEALLOC(tmem, 256); }
#else
    // -------- SIMT fallback --------
    int e = blockIdx.y;
    int n = g_counts[e];
    if (n == 0) return;
    int off = g_offsets[e];
    int ci = blockIdx.x;
    __shared__ float As[16][128];
    __shared__ float Bs[16][64];
    int tid = threadIdx.x;
    int tr = tid & 31, tc = tid >> 5;
    int lr = tid >> 1, lh = (tid & 1) * 8;
    int bkk = tid >> 4, bc = (tid & 15) * 4;
    for (int half = 0; half < 2; half++) {
        const float* wd = Wd + (size_t)e * IDIM * HID + ci * 128 + half * 64;
        for (int row0 = 0; row0 < n; row0 += 128) {
            int rows = min(128, n - row0);
            const float* arow = (lr < rows)
                ? (g_act + (size_t)(off + row0 + lr) * IDIM) : nullptr;
            unsigned long long acc[4][4];
#pragma unroll
            for (int r = 0; r < 4; r++)
#pragma unroll
                for (int p = 0; p < 4; p++) acc[r][p] = 0ull;
            for (int k0 = 0; k0 < IDIM; k0 += 16) {
                float4 av0 = {0,0,0,0}, av1 = {0,0,0,0};
                if (arow) {
                    av0 = *(const float4*)(arow + k0 + lh);
                    av1 = *(const float4*)(arow + k0 + lh + 4);
                }
                float4 bd = *(const float4*)(wd + (size_t)(k0 + bkk) * HID + bc);
                __syncthreads();
                As[lh + 0][lr] = av0.x; As[lh + 1][lr] = av0.y;
                As[lh + 2][lr] = av0.z; As[lh + 3][lr] = av0.w;
                As[lh + 4][lr] = av1.x; As[lh + 5][lr] = av1.y;
                As[lh + 6][lr] = av1.z; As[lh + 7][lr] = av1.w;
                *(float4*)&Bs[bkk][bc] = bd;
                __syncthreads();
#pragma unroll
                for (int kk = 0; kk < 16; kk++) {
                    float4 av = *(const float4*)&As[kk][tr * 4];
                    ulonglong2 b0 = *(const ulonglong2*)&Bs[kk][tc * 8];
                    ulonglong2 b1 = *(const ulonglong2*)&Bs[kk][tc * 8 + 4];
                    unsigned long long aa[4] =
                        { splat2(av.x), splat2(av.y), splat2(av.z), splat2(av.w) };
#pragma unroll
                    for (int r = 0; r < 4; r++) {
                        fma2(acc[r][0], aa[r], b0.x);
                        fma2(acc[r][1], aa[r], b0.y);
                        fma2(acc[r][2], aa[r], b1.x);
                        fma2(acc[r][3], aa[r], b1.y);
                    }
                }
            }
#pragma unroll
            for (int r = 0; r < 4; r++) {
                int lrow = tr * 4 + r;
                if (lrow < rows) {
                    float* dst = g_down + (size_t)(off + row0 + lrow) * HID
                                 + ci * 128 + half * 64 + tc * 8;
                    unsigned long long* dq = (unsigned long long*)dst;
#pragma unroll
                    for (int p = 0; p < 4; p++) dq[p] = acc[r][p];
                }
            }
        }
    }
#endif
}

// ---------------- combine ----------------------------------------------------
__global__ __launch_bounds__(512)
void combine_kernel(float* __restrict__ out) {
    int t = blockIdx.x;
    int h4 = threadIdx.x;
    __shared__ float sw[TOPK];
    __shared__ int   sp[TOPK];
    if (threadIdx.x < TOPK) {
        sw[threadIdx.x] = g_wt[t * TOPK + threadIdx.x];
        sp[threadIdx.x] = g_pos_of[t * TOPK + threadIdx.x];
    }
    __syncthreads();
    float4 acc = make_float4(0.f, 0.f, 0.f, 0.f);
#pragma unroll
    for (int k = 0; k < TOPK; k++) {
        float w = sw[k];
        float4 v = ((const float4*)(g_down + (size_t)sp[k] * HID))[h4];
        acc.x += w * v.x; acc.y += w * v.y; acc.z += w * v.z; acc.w += w * v.w;
    }
    ((float4*)(out + (size_t)t * HID))[h4] = acc;
}

// ---------------- launch -----------------------------------------------------
extern "C" void kernel_launch(void* const* d_in, const int* in_sizes, int n_in,
                              void* d_out, int out_size) {
    const float* x  = (const float*)d_in[0];
    const float* gw = (const float*)d_in[1];
    const float* Wg = (const float*)d_in[2];
    const float* Wu = (const float*)d_in[3];
    const float* Wd = (const float*)d_in[4];
    float* out = (float*)d_out;

    cudaFuncSetAttribute(gemm1_tc, cudaFuncAttributeMaxDynamicSharedMemorySize, SM1_TOT);
    cudaFuncSetAttribute(gemm2_tc, cudaFuncAttributeMaxDynamicSharedMemorySize, SM2_TOT);

    zero_kernel<<<1, 64>>>();
    router_kernel<<<TOKS / 16, 256>>>(x, gw);
    scatter2_kernel<<<1, 512>>>();
    gemm1_tc<<<dim3(IDIM / 128, NEXP), 512, SM1_TOT>>>(x, Wg, Wu);
    gemm2_tc<<<dim3(HID / 128, NEXP), 256, SM2_TOT>>>(Wd);
    combine_kernel<<<TOKS, 512>>>(out);
}

// round 17
// speedup vs baseline: 1.3659x; 1.0312x over previous
#include <cuda_runtime.h>
#include <cstdint>
#include <math.h>

#define TOKS 2048
#define HID  2048
#define NEXP 64
#define IDIM 768
#define TOPK 8
#define NROWS 16384   // TOKS*TOPK

// ---- arch-feature gate: tcgen05 only exists in the sm_103a-specific pass ----
#define HAS_TC 0
#ifdef __CUDA_ARCH_FEAT_SM103_ALL
#undef HAS_TC
#define HAS_TC 1
#endif
#ifdef __CUDA_ARCH_HAS_FEATURE__
#if __CUDA_ARCH_HAS_FEATURE__(SM103_ALL)
#undef HAS_TC
#define HAS_TC 1
#endif
#endif

// ---------------- scratch (device globals; no allocation allowed) ----------
__device__ int   g_counts[NEXP];
__device__ int   g_offsets[NEXP + 1];
__device__ int   g_sel[NROWS];
__device__ float g_wt[NROWS];
__device__ int   g_row_token[NROWS];
__device__ int   g_pos_of[NROWS];
__device__ float g_act[(size_t)NROWS * IDIM];
__device__ float g_down[(size_t)NROWS * HID];

// ---------------- generic helpers -------------------------------------------
__device__ __forceinline__ uint32_t smem_u32(const void* p) {
    uint32_t a;
    asm("{ .reg .u64 t; cvta.to.shared.u64 t, %1; cvt.u32.u64 %0, t; }"
        : "=r"(a) : "l"(p));
    return a;
}
__device__ __forceinline__ uint32_t tf32r(float x) {
    uint32_t u;
    asm("cvt.rna.tf32.f32 %0, %1;" : "=r"(u) : "f"(x));
    return u;
}
__device__ __forceinline__ uint64_t mk_policy_ef() {
    uint64_t pol;
    asm("createpolicy.fractional.L2::evict_first.b64 %0, 1.0;" : "=l"(pol));
    return pol;
}
__device__ __forceinline__ float ldg_ef(const float* p, uint64_t pol) {
    float v;
    asm volatile("ld.global.nc.L2::cache_hint.f32 %0, [%1], %2;"
                 : "=f"(v) : "l"(p), "l"(pol));
    return v;
}
#define SWZ128(o) ((o) ^ (((o) >> 3) & 0x70))

// packed f32x2 (family-wide on sm_10x, fine for compute_103)
__device__ __forceinline__ void fma2(unsigned long long& d, unsigned long long a,
                                     unsigned long long b) {
    asm("fma.rn.f32x2 %0, %1, %2, %0;" : "+l"(d) : "l"(a), "l"(b));
}
__device__ __forceinline__ unsigned long long splat2(float a) {
    unsigned long long r;
    unsigned int u = __float_as_uint(a);
    asm("mov.b64 %0, {%1, %1};" : "=l"(r) : "r"(u));
    return r;
}
__device__ __forceinline__ float2 unpack2(unsigned long long v) {
    unsigned int lo, hi;
    asm("mov.b64 {%0, %1}, %2;" : "=r"(lo), "=r"(hi) : "l"(v));
    return make_float2(__uint_as_float(lo), __uint_as_float(hi));
}

#if HAS_TC
// ---------------- tcgen05 helpers (guarded) ----------------------------------
__device__ __forceinline__ uint32_t elect_one() {
    uint32_t p;
    asm volatile("{\n\t.reg .pred p;\n\telect.sync _|p, 0xFFFFFFFF;\n\t"
                 "selp.b32 %0, 1, 0, p;\n\t}" : "=r"(p));
    return p;
}
#define MBAR_INIT(a, c) \
    asm volatile("mbarrier.init.shared.b64 [%0], %1;" :: "r"(a), "r"(c) : "memory")
#define MBAR_INVAL(a) \
    asm volatile("mbarrier.inval.shared.b64 [%0];" :: "r"(a) : "memory")
#define MBAR_WAIT(a, par) do {                                              \
    uint32_t _m = (a), _p = (par), _d;                                      \
    asm volatile("{\n\t.reg .pred p;\n\t"                                   \
        "mbarrier.try_wait.parity.acquire.cta.shared::cta.b64 p, [%1], %2;\n\t" \
        "selp.b32 %0, 1, 0, p;\n\t}" : "=r"(_d) : "r"(_m), "r"(_p) : "memory"); \
    if (!_d) {                                                              \
        asm volatile("{\n\t.reg .pred P1;\n\t"                              \
            "W%=:\n\t"                                                       \
            "mbarrier.try_wait.parity.acquire.cta.shared::cta.b64 P1, [%0], %1, 0x989680;\n\t" \
            "@P1 bra.uni D%=;\n\tbra.uni W%=;\n\tD%=:\n\t}"                  \
            :: "r"(_m), "r"(_p) : "memory");                                \
    }                                                                       \
} while (0)

#define TC_ALLOC(sa, n) \
    asm volatile("tcgen05.alloc.cta_group::1.sync.aligned.shared::cta.b32 [%0], %1;" \
                 :: "r"(sa), "r"((uint32_t)(n)) : "memory")
#define TC_DEALLOC(t, n) \
    asm volatile("tcgen05.dealloc.cta_group::1.sync.aligned.b32 %0, %1;" \
                 :: "r"(t), "r"((uint32_t)(n)))
#define TC_RELINQ() \
    asm volatile("tcgen05.relinquish_alloc_permit.cta_group::1.sync.aligned;")
#define TC_COMMIT(mb) \
    asm volatile("tcgen05.commit.cta_group::1.mbarrier::arrive::one.shared::cluster.b64 [%0];" \
                 :: "r"(mb) : "memory")
#define TC_FENCE_BEFORE() asm volatile("tcgen05.fence::before_thread_sync;" ::: "memory")
#define TC_FENCE_AFTER()  asm volatile("tcgen05.fence::after_thread_sync;" ::: "memory")
#define TC_WAIT_LD()      asm volatile("tcgen05.wait::ld.sync.aligned;" ::: "memory")
#define FENCE_ASYNC()     asm volatile("fence.proxy.async.shared::cta;" ::: "memory")

#define LDTM32(r, a)                                                         \
    asm volatile("tcgen05.ld.sync.aligned.32x32b.x32.b32 "                   \
        "{%0,%1,%2,%3,%4,%5,%6,%7,%8,%9,%10,%11,%12,%13,%14,%15,"            \
        "%16,%17,%18,%19,%20,%21,%22,%23,%24,%25,%26,%27,%28,%29,%30,%31}, [%32];" \
        : "=r"((r)[0]),"=r"((r)[1]),"=r"((r)[2]),"=r"((r)[3]),               \
          "=r"((r)[4]),"=r"((r)[5]),"=r"((r)[6]),"=r"((r)[7]),               \
          "=r"((r)[8]),"=r"((r)[9]),"=r"((r)[10]),"=r"((r)[11]),             \
          "=r"((r)[12]),"=r"((r)[13]),"=r"((r)[14]),"=r"((r)[15]),           \
          "=r"((r)[16]),"=r"((r)[17]),"=r"((r)[18]),"=r"((r)[19]),           \
          "=r"((r)[20]),"=r"((r)[21]),"=r"((r)[22]),"=r"((r)[23]),           \
          "=r"((r)[24]),"=r"((r)[25]),"=r"((r)[26]),"=r"((r)[27]),           \
          "=r"((r)[28]),"=r"((r)[29]),"=r"((r)[30]),"=r"((r)[31])            \
        : "r"(a))

#define LDTM16(r, a)                                                         \
    asm volatile("tcgen05.ld.sync.aligned.32x32b.x16.b32 "                   \
        "{%0,%1,%2,%3,%4,%5,%6,%7,%8,%9,%10,%11,%12,%13,%14,%15}, [%16];"    \
        : "=r"((r)[0]),"=r"((r)[1]),"=r"((r)[2]),"=r"((r)[3]),               \
          "=r"((r)[4]),"=r"((r)[5]),"=r"((r)[6]),"=r"((r)[7]),               \
          "=r"((r)[8]),"=r"((r)[9]),"=r"((r)[10]),"=r"((r)[11]),             \
          "=r"((r)[12]),"=r"((r)[13]),"=r"((r)[14]),"=r"((r)[15])            \
        : "r"(a))

__device__ __forceinline__ uint64_t mk_desc(uint32_t addr) {
    const uint64_t base = (uint64_t(2) << 61) | (uint64_t(1) << 46)
                        | (uint64_t(64) << 32) | (uint64_t(1) << 16);
    return base | ((uint64_t)(addr >> 4) & 0x3FFF);
}
#define IDESC_TF32_128 ((1u << 4) | (2u << 7) | (2u << 10) | (16u << 17) | (8u << 24))
__device__ __forceinline__ void mma_tf32(uint32_t d, uint64_t a, uint64_t b,
                                         uint32_t en) {
    asm volatile("{\n\t.reg .pred p;\n\tsetp.ne.u32 p, %5, 0;\n\t"
        "tcgen05.mma.cta_group::1.kind::tf32 [%0], %1, %2, %3, {%4,%4,%4,%4}, p;\n\t}"
        :: "r"(d), "l"(a), "l"(b), "r"(IDESC_TF32_128), "r"(0u), "r"(en)
        : "memory");
}
#endif // HAS_TC

// ---------------- setup kernels ----------------------------------------------
__global__ void zero_kernel() {
    int t = threadIdx.x;
    if (t < NEXP) g_counts[t] = 0;
}

// merged scan + scatter
__global__ __launch_bounds__(512)
void scatter2_kernel() {
    __shared__ int soff[NEXP];
    __shared__ int scur[NEXP];
    int tid = threadIdx.x;
    if (tid == 0) {
        int s = 0;
        for (int e = 0; e < NEXP; e++) {
            soff[e] = s; g_offsets[e] = s; s += g_counts[e];
        }
        g_offsets[NEXP] = s;
    }
    if (tid < NEXP) scur[tid] = 0;
    __syncthreads();
#pragma unroll
    for (int it = 0; it < NROWS / 512; it++) {
        int i = it * 512 + tid;
        int e = g_sel[i];
        int p = soff[e] + atomicAdd(&scur[e], 1);
        g_row_token[p] = i >> 3;
        g_pos_of[i] = p;
    }
}

// ---------------- router -----------------------------------------------------
__global__ void router_kernel(const float* __restrict__ x,
                              const float* __restrict__ gw) {
    __shared__ float xs[16][64];
    __shared__ float gws[64][64];
    __shared__ float lg[16][64];
    int tid = threadIdx.x;
    int t0 = blockIdx.x * 16;
    int tok = tid >> 4, eg = tid & 15;
    float a0 = 0.f, a1 = 0.f, a2 = 0.f, a3 = 0.f;
    for (int h0 = 0; h0 < HID; h0 += 64) {
#pragma unroll
        for (int i = 0; i < 4; i++) {
            int idx = i * 256 + tid;
            int row = idx >> 4, col = (idx & 15) * 4;
            *(float4*)&gws[row][col] =
                *(const float4*)(gw + (size_t)(h0 + row) * NEXP + col);
        }
        {
            int row = tid >> 4, col = (tid & 15) * 4;
            *(float4*)&xs[row][col] =
                *(const float4*)(x + (size_t)(t0 + row) * HID + h0 + col);
        }
        __syncthreads();
#pragma unroll 8
        for (int hh = 0; hh < 64; hh++) {
            float xv = xs[tok][hh];
            float4 g4 = *(const float4*)&gws[hh][eg * 4];
            a0 += xv * g4.x; a1 += xv * g4.y; a2 += xv * g4.z; a3 += xv * g4.w;
        }
        __syncthreads();
    }
    lg[tok][eg * 4 + 0] = a0; lg[tok][eg * 4 + 1] = a1;
    lg[tok][eg * 4 + 2] = a2; lg[tok][eg * 4 + 3] = a3;
    __syncthreads();
    if (tid < 16) {
        int t = t0 + tid;
        float vals[TOPK]; int sel[TOPK];
#pragma unroll
        for (int k = 0; k < TOPK; k++) {
            float best = -3.4e38f; int bi = 0;
            for (int e2 = 0; e2 < NEXP; e2++) {
                float v = lg[tid][e2];
                if (v > best) { best = v; bi = e2; }
            }
            vals[k] = best; sel[k] = bi;
            lg[tid][bi] = -3.4e38f;
        }
        float m = vals[0], ex[TOPK], s = 0.f;
#pragma unroll
        for (int k = 0; k < TOPK; k++) { ex[k] = expf(vals[k] - m); s += ex[k]; }
        float inv = 1.0f / s;
#pragma unroll
        for (int k = 0; k < TOPK; k++) {
            g_sel[t * TOPK + k] = sel[k];
            g_wt[t * TOPK + k] = ex[k] * inv;
            atomicAdd(&g_counts[sel[k]], 1);
        }
    }
}

// dynamic smem: header 2KB + double-buffered tiles
#define SM1_TOT (2048 + 2 * (32768 + 16384 + 16384))   // 133120
#define SM2_TOT (2048 + 2 * (32768 + 16384))           // 100352

// ---------------- grouped GEMM 1: act = silu(x@Wg)*(x@Wu) --------------------
// grid (IDIM/128, NEXP), 1024 threads (32 warps). Double-buffered mainloop.
__global__ __launch_bounds__(1024, 1)
void gemm1_tc(const float* __restrict__ x,
              const float* __restrict__ Wg,
              const float* __restrict__ Wu) {
#if HAS_TC
    extern __shared__ char smem[];
    int e = blockIdx.y, ci = blockIdx.x;
    int n = g_counts[e];
    if (n == 0) return;
    int off = g_offsets[e];
    int tid = threadIdx.x;
    uint32_t sb = smem_u32(smem);
    uint32_t mb0 = sb + 8, mb1 = sb + 16;
    uint32_t aA0 = (sb + 1024 + 1023) & ~1023u;
    uint32_t aBG0 = aA0 + 32768, aBU0 = aBG0 + 16384;
    uint32_t aA1 = aBU0 + 16384;
    uint32_t aBG1 = aA1 + 32768, aBU1 = aBG1 + 16384;
    char* base = smem - sb;     // char* such that base + smem_addr = generic ptr
    uint64_t pol = mk_policy_ef();

    if (tid < 32) TC_ALLOC(sb, 512);
    if (tid == 0) { MBAR_INIT(mb0, 1); MBAR_INIT(mb1, 1); }
    __syncthreads();
    uint32_t tmem;
    asm volatile("ld.shared.b32 %0, [%1];" : "=r"(tmem) : "r"(sb));

    const float* wgb = Wg + (size_t)e * HID * IDIM + ci * 128;
    const float* wub = Wu + (size_t)e * HID * IDIM + ci * 128;
    // B mapping: 2048 cells (2 mat x 128 n x 8 kc), 2 per thread
    const int nn  = tid & 127;            // B n-row
    const int kcp = (tid >> 7) & 3;       // kc pair: kc = kcp*2, kcp*2+1
    const float* wmb = (tid >> 9) ? wub : wgb;
    // A mapping: 2048 cells (256 rows x 8 kc), 2 per thread
    const int kcA  = tid & 7;             // A k-cell
    const int rowA = tid >> 3;            // rows rowA, rowA+128
    uint32_t ph0 = 0, ph1 = 0;
    int used0 = 0, used1 = 0;

#define G1_CHUNK(CH, AA, ABG, ABU, MB, PH, USED, FIRSTC) do {               \
    int k0 = (CH) * 32;                                                     \
    float4 av[2];                                                           \
    _Pragma("unroll")                                                       \
    for (int i = 0; i < 2; i++)                                             \
        av[i] = aptr[i] ? *(const float4*)(aptr[i] + k0 + kcA * 4)          \
                        : make_float4(0.f, 0.f, 0.f, 0.f);                  \
    float bv[2][4];                                                         \
    _Pragma("unroll")                                                       \
    for (int c = 0; c < 2; c++) {                                           \
        const float* wb = wmb + (size_t)(k0 + (kcp * 2 + c) * 4) * IDIM + nn; \
        _Pragma("unroll")                                                   \
        for (int j = 0; j < 4; j++) bv[c][j] = ldg_ef(wb + (size_t)j * IDIM, pol); \
    }                                                                       \
    if (USED) { MBAR_WAIT(MB, PH); PH ^= 1; }                               \
    USED = 1;                                                               \
    _Pragma("unroll")                                                       \
    for (int i = 0; i < 2; i++) {                                           \
        int row = i * 128 + rowA;                                           \
        uint32_t o = SWZ128((uint32_t)(row * 128 + kcA * 16));              \
        uint4 v = { tf32r(av[i].x), tf32r(av[i].y),                         \
                    tf32r(av[i].z), tf32r(av[i].w) };                       \
        *(uint4*)(base + (AA) + o) = v;                                     \
    }                                                                       \
    {                                                                       \
        char* bbase = base + ((tid >> 9) ? (ABU) : (ABG));                  \
        _Pragma("unroll")                                                   \
        for (int c = 0; c < 2; c++) {                                       \
            uint32_t o = SWZ128((uint32_t)(nn * 128 + (kcp * 2 + c) * 16)); \
            uint4 v = { tf32r(bv[c][0]), tf32r(bv[c][1]),                   \
                        tf32r(bv[c][2]), tf32r(bv[c][3]) };                 \
            *(uint4*)(bbase + o) = v;                                       \
        }                                                                   \
    }                                                                       \
    __syncthreads();                                                        \
    if (tid < 32) {                                                         \
        FENCE_ASYNC();                                                      \
        if (elect_one()) {                                                  \
            uint64_t da0 = mk_desc(AA);                                     \
            uint64_t da1 = mk_desc((AA) + 128 * 128);                       \
            uint64_t dbg = mk_desc(ABG);                                    \
            uint64_t dbu = mk_desc(ABU);                                    \
            _Pragma("unroll")                                               \
            for (int s = 0; s < 4; s++) {                                   \
                uint32_t en = ((FIRSTC) && s == 0) ? 0u : 1u;               \
                uint64_t so = 2 * s;                                        \
                mma_tf32(tmem + 0,   da0 + so, dbg + so, en);               \
                mma_tf32(tmem + 128, da0 + so, dbu + so, en);               \
                mma_tf32(tmem + 256, da1 + so, dbg + so, en);               \
                mma_tf32(tmem + 384, da1 + so, dbu + so, en);               \
            }                                                               \
            TC_COMMIT(MB);                                                  \
        }                                                                   \
    }                                                                       \
} while (0)

    for (int row0 = 0; row0 < n; row0 += 256) {
        const float* aptr[2];
#pragma unroll
        for (int i = 0; i < 2; i++) {
            int gr = row0 + i * 128 + rowA;
            aptr[i] = (gr < n) ? x + (size_t)g_row_token[off + gr] * HID : nullptr;
        }
        for (int ch = 0; ch < HID / 32; ch += 2) {
            G1_CHUNK(ch,     aA0, aBG0, aBU0, mb0, ph0, used0, ch == 0);
            G1_CHUNK(ch + 1, aA1, aBG1, aBU1, mb1, ph1, used1, 0);
        }
        // last chunk (63) used buffer 1
        MBAR_WAIT(mb1, ph1); ph1 ^= 1; used1 = 0;
        TC_FENCE_AFTER();
        // 32 warps: w -> subp = w&3, rg = (w>>2)&1, colblock = w>>3 (0..3)
        int w = tid >> 5, lane = tid & 31;
        int subp = w & 3;
        int rg = (w >> 2) & 1;
        int cb = (w >> 3) * 32;
        uint32_t wo = ((uint32_t)subp) << 21;
        int grow = row0 + rg * 128 + subp * 32 + lane;
        bool valid = grow < n;
        size_t orow = (size_t)(off + grow) * IDIM + ci * 128;
#pragma unroll
        for (int h = 0; h < 2; h++) {
            uint32_t rgv[16], ruv[16];
            LDTM16(rgv, tmem + rg * 256 + cb + h * 16 + wo);
            LDTM16(ruv, tmem + rg * 256 + 128 + cb + h * 16 + wo);
            TC_WAIT_LD();
            if (valid) {
#pragma unroll
                for (int c = 0; c < 16; c += 4) {
                    uint4 o;
                    float gg, uu, a;
                    gg = __uint_as_float(rgv[c + 0]); uu = __uint_as_float(ruv[c + 0]);
                    a = (gg / (1.f + expf(-gg))) * uu; o.x = tf32r(a);
                    gg = __uint_as_float(rgv[c + 1]); uu = __uint_as_float(ruv[c + 1]);
                    a = (gg / (1.f + expf(-gg))) * uu; o.y = tf32r(a);
                    gg = __uint_as_float(rgv[c + 2]); uu = __uint_as_float(ruv[c + 2]);
                    a = (gg / (1.f + expf(-gg))) * uu; o.z = tf32r(a);
                    gg = __uint_as_float(rgv[c + 3]); uu = __uint_as_float(ruv[c + 3]);
                    a = (gg / (1.f + expf(-gg))) * uu; o.w = tf32r(a);
                    *(uint4*)(g_act + orow + cb + h * 16 + c) = o;
                }
            }
        }
        TC_FENCE_BEFORE();
        __syncthreads();
    }
#undef G1_CHUNK
    if (tid == 0) { MBAR_INVAL(mb0); MBAR_INVAL(mb1); }
    __syncthreads();
    if (tid < 32) { TC_RELINQ(); TC_DEALLOC(tmem, 512); }
#else
    // -------- SIMT fallback (guarded for 1024-thread launch) --------
    int e = blockIdx.y;
    int n = g_counts[e];
    if (n == 0) return;
    int off = g_offsets[e];
    int ci = blockIdx.x;
    __shared__ float As[16][128];
    __shared__ float Bgs[16][64];
    __shared__ float Bus[16][64];
    int tid = threadIdx.x;
    bool act = tid < 256;
    int tr = tid & 31, tc = (tid >> 5) & 7;
    int lr = (tid >> 1) & 127, lh = (tid & 1) * 8;
    int bkk = (tid >> 4) & 15, bc = (tid & 15) * 4;
    for (int half = 0; half < 2; half++) {
        const float* wg = Wg + (size_t)e * HID * IDIM + ci * 128 + half * 64;
        const float* wu = Wu + (size_t)e * HID * IDIM + ci * 128 + half * 64;
        for (int row0 = 0; row0 < n; row0 += 128) {
            int rows = min(128, n - row0);
            const float* xrow = (act && lr < rows)
                ? (x + (size_t)g_row_token[off + row0 + lr] * HID) : nullptr;
            unsigned long long accg[4][4], accu[4][4];
#pragma unroll
            for (int r = 0; r < 4; r++)
#pragma unroll
                for (int p = 0; p < 4; p++) { accg[r][p] = 0ull; accu[r][p] = 0ull; }
            for (int k0 = 0; k0 < HID; k0 += 16) {
                float4 av0 = {0,0,0,0}, av1 = {0,0,0,0};
                float4 bg = {0,0,0,0}, bu = {0,0,0,0};
                if (xrow) {
                    av0 = *(const float4*)(xrow + k0 + lh);
                    av1 = *(const float4*)(xrow + k0 + lh + 4);
                }
                if (act) {
                    bg = *(const float4*)(wg + (size_t)(k0 + bkk) * IDIM + bc);
                    bu = *(const float4*)(wu + (size_t)(k0 + bkk) * IDIM + bc);
                }
                __syncthreads();
                if (act) {
                    As[lh + 0][lr] = av0.x; As[lh + 1][lr] = av0.y;
                    As[lh + 2][lr] = av0.z; As[lh + 3][lr] = av0.w;
                    As[lh + 4][lr] = av1.x; As[lh + 5][lr] = av1.y;
                    As[lh + 6][lr] = av1.z; As[lh + 7][lr] = av1.w;
                    *(float4*)&Bgs[bkk][bc] = bg;
                    *(float4*)&Bus[bkk][bc] = bu;
                }
                __syncthreads();
                if (act) {
#pragma unroll
                    for (int kk = 0; kk < 16; kk++) {
                        float4 av = *(const float4*)&As[kk][tr * 4];
                        ulonglong2 bg0 = *(const ulonglong2*)&Bgs[kk][tc * 8];
                        ulonglong2 bg1 = *(const ulonglong2*)&Bgs[kk][tc * 8 + 4];
                        ulonglong2 bu0 = *(const ulonglong2*)&Bus[kk][tc * 8];
                        ulonglong2 bu1 = *(const ulonglong2*)&Bus[kk][tc * 8 + 4];
                        unsigned long long aa[4] =
                            { splat2(av.x), splat2(av.y), splat2(av.z), splat2(av.w) };
#pragma unroll
                        for (int r = 0; r < 4; r++) {
                            fma2(accg[r][0], aa[r], bg0.x);
                            fma2(accg[r][1], aa[r], bg0.y);
                            fma2(accg[r][2], aa[r], bg1.x);
                            fma2(accg[r][3], aa[r], bg1.y);
                            fma2(accu[r][0], aa[r], bu0.x);
                            fma2(accu[r][1], aa[r], bu0.y);
                            fma2(accu[r][2], aa[r], bu1.x);
                            fma2(accu[r][3], aa[r], bu1.y);
                        }
                    }
                }
            }
            if (act) {
#pragma unroll
                for (int r = 0; r < 4; r++) {
                    int lrow = tr * 4 + r;
                    if (lrow < rows) {
                        float* dst = g_act + (size_t)(off + row0 + lrow) * IDIM
                                     + ci * 128 + half * 64 + tc * 8;
#pragma unroll
                        for (int p = 0; p < 4; p++) {
                            float2 g = unpack2(accg[r][p]);
                            float2 u = unpack2(accu[r][p]);
                            dst[p * 2 + 0] = (g.x / (1.0f + expf(-g.x))) * u.x;
                            dst[p * 2 + 1] = (g.y / (1.0f + expf(-g.y))) * u.y;
                        }
                    }
                }
            }
        }
    }
#endif
}

// ---------------- grouped GEMM 2: down = act @ Wd ----------------------------
// grid (HID/128, NEXP), 256 threads, 2 CTAs/SM. Double-buffered mainloop.
__global__ __launch_bounds__(256, 2)
void gemm2_tc(const float* __restrict__ Wd) {
#if HAS_TC
    extern __shared__ char smem[];
    int e = blockIdx.y, ci = blockIdx.x;
    int n = g_counts[e];
    if (n == 0) return;
    int off = g_offsets[e];
    int tid = threadIdx.x;
    uint32_t sb = smem_u32(smem);
    uint32_t mb0 = sb + 8, mb1 = sb + 16;
    uint32_t aA0 = (sb + 1024 + 1023) & ~1023u;
    uint32_t aB0 = aA0 + 32768;
    uint32_t aA1 = aB0 + 16384;
    uint32_t aB1 = aA1 + 32768;
    char* base = smem - sb;
    uint64_t pol = mk_policy_ef();

    if (tid < 32) TC_ALLOC(sb, 256);
    if (tid == 0) { MBAR_INIT(mb0, 1); MBAR_INIT(mb1, 1); }
    __syncthreads();
    uint32_t tmem;
    asm volatile("ld.shared.b32 %0, [%1];" : "=r"(tmem) : "r"(sb));

    const float* wdb = Wd + (size_t)e * IDIM * HID + ci * 128;
    const int nn = tid & 127;
    const int kcA = tid & 7;
    uint32_t ph0 = 0, ph1 = 0;
    int used0 = 0, used1 = 0;

#define G2_CHUNK(CH, AA, AB, MB, PH, USED, FIRSTC) do {                     \
    int k0 = (CH) * 32;                                                     \
    uint4 av[8];                                                            \
    _Pragma("unroll")                                                       \
    for (int i = 0; i < 8; i++)                                             \
        av[i] = aptr[i] ? *(const uint4*)(aptr[i] + k0 + kcA * 4)           \
                        : make_uint4(0u, 0u, 0u, 0u);                       \
    float bv[4][4];                                                         \
    _Pragma("unroll")                                                       \
    for (int i = 0; i < 4; i++) {                                           \
        int kc = i * 2 + (tid >> 7);                                        \
        const float* wb = wdb + (size_t)(k0 + kc * 4) * HID + nn;           \
        _Pragma("unroll")                                                   \
        for (int j = 0; j < 4; j++) bv[i][j] = ldg_ef(wb + (size_t)j * HID, pol); \
    }                                                                       \
    if (USED) { MBAR_WAIT(MB, PH); PH ^= 1; }                               \
    USED = 1;                                                               \
    _Pragma("unroll")                                                       \
    for (int i = 0; i < 8; i++) {                                           \
        int row = i * 32 + (tid >> 3);                                      \
        uint32_t o = SWZ128((uint32_t)(row * 128 + kcA * 16));              \
        *(uint4*)(base + (AA) + o) = av[i];                                 \
    }                                                                       \
    _Pragma("unroll")                                                       \
    for (int i = 0; i < 4; i++) {                                           \
        int kc = i * 2 + (tid >> 7);                                        \
        uint32_t o = SWZ128((uint32_t)(nn * 128 + kc * 16));                \
        uint4 v = { tf32r(bv[i][0]), tf32r(bv[i][1]),                       \
                    tf32r(bv[i][2]), tf32r(bv[i][3]) };                     \
        *(uint4*)(base + (AB) + o) = v;                                     \
    }                                                                       \
    __syncthreads();                                                        \
    if (tid < 32) {                                                         \
        FENCE_ASYNC();                                                      \
        if (elect_one()) {                                                  \
            uint64_t da0 = mk_desc(AA);                                     \
            uint64_t da1 = mk_desc((AA) + 128 * 128);                       \
            uint64_t db  = mk_desc(AB);                                     \
            _Pragma("unroll")                                               \
            for (int s = 0; s < 4; s++) {                                   \
                uint32_t en = ((FIRSTC) && s == 0) ? 0u : 1u;               \
                uint64_t so = 2 * s;                                        \
                mma_tf32(tmem + 0,   da0 + so, db + so, en);                \
                mma_tf32(tmem + 128, da1 + so, db + so, en);                \
            }                                                               \
            TC_COMMIT(MB);                                                  \
        }                                                                   \
    }                                                                       \
} while (0)

    for (int row0 = 0; row0 < n; row0 += 256) {
        const float* aptr[8];
#pragma unroll
        for (int i = 0; i < 8; i++) {
            int gr = row0 + i * 32 + (tid >> 3);
            aptr[i] = (gr < n) ? g_act + (size_t)(off + gr) * IDIM : nullptr;
        }
        for (int ch = 0; ch < IDIM / 32; ch += 2) {
            G2_CHUNK(ch,     aA0, aB0, mb0, ph0, used0, ch == 0);
            G2_CHUNK(ch + 1, aA1, aB1, mb1, ph1, used1, 0);
        }
        // last chunk (23) used buffer 1
        MBAR_WAIT(mb1, ph1); ph1 ^= 1; used1 = 0;
        TC_FENCE_AFTER();
        int rg = tid >> 7;
        uint32_t wo = ((uint32_t)((tid >> 5) & 3)) << 21;
        int grow = row0 + rg * 128 + (tid & 127);
        bool valid = grow < n;
        size_t orow = (size_t)(off + grow) * HID + ci * 128;
#pragma unroll
        for (int cb = 0; cb < 128; cb += 32) {
            uint32_t dv[32];
            LDTM32(dv, tmem + rg * 128 + cb + wo);
            TC_WAIT_LD();
            if (valid) {
#pragma unroll
                for (int c = 0; c < 32; c += 4) {
                    uint4 o = { dv[c], dv[c + 1], dv[c + 2], dv[c + 3] };
                    *(uint4*)(g_down + orow + cb + c) = o;
                }
            }
        }
        TC_FENCE_BEFORE();
        __syncthreads();
    }
#undef G2_CHUNK
    if (tid == 0) { MBAR_INVAL(mb0); MBAR_INVAL(mb1); }
    __syncthreads();
    if (tid < 32) { TC_RELINQ(); TC_DEALLOC(tmem, 256); }
#else
    // -------- SIMT fallback --------
    int e = blockIdx.y;
    int n = g_counts[e];
    if (n == 0) return;
    int off = g_offsets[e];
    int ci = blockIdx.x;
    __shared__ float As[16][128];
    __shared__ float Bs[16][64];
    int tid = threadIdx.x;
    int tr = tid & 31, tc = tid >> 5;
    int lr = tid >> 1, lh = (tid & 1) * 8;
    int bkk = tid >> 4, bc = (tid & 15) * 4;
    for (int half = 0; half < 2; half++) {
        const float* wd = Wd + (size_t)e * IDIM * HID + ci * 128 + half * 64;
        for (int row0 = 0; row0 < n; row0 += 128) {
            int rows = min(128, n - row0);
            const float* arow = (lr < rows)
                ? (g_act + (size_t)(off + row0 + lr) * IDIM) : nullptr;
            unsigned long long acc[4][4];
#pragma unroll
            for (int r = 0; r < 4; r++)
#pragma unroll
                for (int p = 0; p < 4; p++) acc[r][p] = 0ull;
            for (int k0 = 0; k0 < IDIM; k0 += 16) {
                float4 av0 = {0,0,0,0}, av1 = {0,0,0,0};
                if (arow) {
                    av0 = *(const float4*)(arow + k0 + lh);
                    av1 = *(const float4*)(arow + k0 + lh + 4);
                }
                float4 bd = *(const float4*)(wd + (size_t)(k0 + bkk) * HID + bc);
                __syncthreads();
                As[lh + 0][lr] = av0.x; As[lh + 1][lr] = av0.y;
                As[lh + 2][lr] = av0.z; As[lh + 3][lr] = av0.w;
                As[lh + 4][lr] = av1.x; As[lh + 5][lr] = av1.y;
                As[lh + 6][lr] = av1.z; As[lh + 7][lr] = av1.w;
                *(float4*)&Bs[bkk][bc] = bd;
                __syncthreads();
#pragma unroll
                for (int kk = 0; kk < 16; kk++) {
                    float4 av = *(const float4*)&As[kk][tr * 4];
                    ulonglong2 b0 = *(const ulonglong2*)&Bs[kk][tc * 8];
                    ulonglong2 b1 = *(const ulonglong2*)&Bs[kk][tc * 8 + 4];
                    unsigned long long aa[4] =
                        { splat2(av.x), splat2(av.y), splat2(av.z), splat2(av.w) };
#pragma unroll
                    for (int r = 0; r < 4; r++) {
                        fma2(acc[r][0], aa[r], b0.x);
                        fma2(acc[r][1], aa[r], b0.y);
                        fma2(acc[r][2], aa[r], b1.x);
                        fma2(acc[r][3], aa[r], b1.y);
                    }
                }
            }
#pragma unroll
            for (int r = 0; r < 4; r++) {
                int lrow = tr * 4 + r;
                if (lrow < rows) {
                    float* dst = g_down + (size_t)(off + row0 + lrow) * HID
                                 + ci * 128 + half * 64 + tc * 8;
                    unsigned long long* dq = (unsigned long long*)dst;
#pragma unroll
                    for (int p = 0; p < 4; p++) dq[p] = acc[r][p];
                }
            }
        }
    }
#endif
}

// ---------------- combine ----------------------------------------------------
__global__ __launch_bounds__(512)
void combine_kernel(float* __restrict__ out) {
    int t = blockIdx.x;
    int h4 = threadIdx.x;
    __shared__ float sw[TOPK];
    __shared__ int   sp[TOPK];
    if (threadIdx.x < TOPK) {
        sw[threadIdx.x] = g_wt[t * TOPK + threadIdx.x];
        sp[threadIdx.x] = g_pos_of[t * TOPK + threadIdx.x];
    }
    __syncthreads();
    float4 acc = make_float4(0.f, 0.f, 0.f, 0.f);
#pragma unroll
    for (int k = 0; k < TOPK; k++) {
        float w = sw[k];
        float4 v = ((const float4*)(g_down + (size_t)sp[k] * HID))[h4];
        acc.x += w * v.x; acc.y += w * v.y; acc.z += w * v.z; acc.w += w * v.w;
    }
    ((float4*)(out + (size_t)t * HID))[h4] = acc;
}

// ---------------- launch -----------------------------------------------------
extern "C" void kernel_launch(void* const* d_in, const int* in_sizes, int n_in,
                              void* d_out, int out_size) {
    const float* x  = (const float*)d_in[0];
    const float* gw = (const float*)d_in[1];
    const float* Wg = (const float*)d_in[2];
    const float* Wu = (const float*)d_in[3];
    const float* Wd = (const float*)d_in[4];
    float* out = (float*)d_out;

    cudaFuncSetAttribute(gemm1_tc, cudaFuncAttributeMaxDynamicSharedMemorySize, SM1_TOT);
    cudaFuncSetAttribute(gemm2_tc, cudaFuncAttributeMaxDynamicSharedMemorySize, SM2_TOT);

    zero_kernel<<<1, 64>>>();
    router_kernel<<<TOKS / 16, 256>>>(x, gw);
    scatter2_kernel<<<1, 512>>>();
    gemm1_tc<<<dim3(IDIM / 128, NEXP), 1024, SM1_TOT>>>(x, Wg, Wu);
    gemm2_tc<<<dim3(HID / 128, NEXP), 256, SM2_TOT>>>(Wd);
    combine_kernel<<<TOKS, 512>>>(out);
}